// round 1
// baseline (speedup 1.0000x reference)
#include <cuda_runtime.h>
#include <math.h>

// ---------------------------------------------------------------------------
// NeuralSplineFlow forward, fp32 SIMT baseline.
//
// Structural simplifications derived from the reference masks:
//  * M0 masks input col 1 -> MADE depends only on scalar out0.
//  * MF masks Wf rows [0,PM) -> dim-0 spline params are per-layer constants
//    (bias only) -> the first autoregressive pass is redundant.
// Per layer: out0 = RQS_inv(y0; const), h = out0*W0col + b0, two residual
// blocks (4x [128x128] GEMM), p1 = h @ Wf[PM:].T, out1 = RQS_inv(y1; p1),
// 2x2 LU solve (analytic inverse, precomputed), permutation.
// ---------------------------------------------------------------------------

#define BATCH   262144
#define NLAYER  16
#define HDIM    128
#define NBINS   8
#define PMVAL   23
#define TBV     3.0f
#define MINWV   0.001f
#define MINDV   0.001f
#define LUEPS   0.001f
#define INV_SQH 0.08838834764831843f   // 1/sqrt(128)
#define PAD     4
#define LDA     (HDIM + PAD)           // 132 floats per smem row
#define WFN     24                     // padded N for the Wf GEMM (23 real)

#define SMEM_BYTES (3 * HDIM * LDA * 4)

// ----------------------------- device scratch ------------------------------
__device__ float g_state[BATCH * 2];
__device__ float g_ld[BATCH];
__device__ float g_WresT[NLAYER * 4 * HDIM * HDIM];  // [layer][gemm][k][n]
__device__ float g_WfT[NLAYER * HDIM * WFN];          // [layer][k][24]
__device__ float g_cw0[NLAYER * 9];
__device__ float g_w0[NLAYER * 8];
__device__ float g_ch0[NLAYER * 9];
__device__ float g_h0[NLAYER * 8];
__device__ float g_d0[NLAYER * 9];
__device__ float g_invW[NLAYER * 4];
__device__ float g_ldinit;

// ----------------------------- math helpers --------------------------------
__device__ __forceinline__ float softplusf(float x) {
    return fmaxf(x, 0.f) + log1pf(expf(-fabsf(x)));
}

// Build RQS tables from raw params (uw[8], uh[8], ud[7]).
__device__ void build_params(const float* uw, const float* uh, const float* ud,
                             float* cw, float* w, float* ch, float* hh, float* dd) {
    // widths
    {
        float mx = uw[0];
        #pragma unroll
        for (int k = 1; k < NBINS; k++) mx = fmaxf(mx, uw[k]);
        float e[NBINS]; float s = 0.f;
        #pragma unroll
        for (int k = 0; k < NBINS; k++) { e[k] = expf(uw[k] - mx); s += e[k]; }
        float inv = 1.f / s;
        cw[0] = -TBV;
        float cum = 0.f;
        #pragma unroll
        for (int k = 0; k < NBINS; k++) {
            float wk = MINWV + (1.f - MINWV * NBINS) * e[k] * inv;
            cum += wk;
            cw[k + 1] = 2.f * TBV * cum - TBV;
        }
        cw[NBINS] = TBV;
        #pragma unroll
        for (int k = 0; k < NBINS; k++) w[k] = cw[k + 1] - cw[k];
    }
    // heights
    {
        float mx = uh[0];
        #pragma unroll
        for (int k = 1; k < NBINS; k++) mx = fmaxf(mx, uh[k]);
        float e[NBINS]; float s = 0.f;
        #pragma unroll
        for (int k = 0; k < NBINS; k++) { e[k] = expf(uh[k] - mx); s += e[k]; }
        float inv = 1.f / s;
        ch[0] = -TBV;
        float cum = 0.f;
        #pragma unroll
        for (int k = 0; k < NBINS; k++) {
            float hk = MINWV + (1.f - MINWV * NBINS) * e[k] * inv;
            cum += hk;
            ch[k + 1] = 2.f * TBV * cum - TBV;
        }
        ch[NBINS] = TBV;
        #pragma unroll
        for (int k = 0; k < NBINS; k++) hh[k] = ch[k + 1] - ch[k];
    }
    // derivatives: boundary = MIND + softplus(DCONST) == 1.0
    dd[0] = 1.0f;
    #pragma unroll
    for (int k = 0; k < 7; k++) dd[k + 1] = MINDV + softplusf(ud[k]);
    dd[NBINS] = 1.0f;
}

// RQS inverse for a single scalar.
__device__ void rqs_inverse(float y, const float* cw, const float* w,
                            const float* ch, const float* hh, const float* dd,
                            float& xout, float& ldout) {
    bool inside = (y >= -TBV) && (y <= TBV);
    float yc = fminf(fmaxf(y, -TBV), TBV);
    int idx = 0;
    #pragma unroll
    for (int k = 1; k <= NBINS; k++) idx += (yc >= ch[k]) ? 1 : 0;
    idx = min(idx, NBINS - 1);

    float yk = ch[idx], hk = hh[idx], xk = cw[idx], wk = w[idx];
    float dk = dd[idx], dk1 = dd[idx + 1];
    float sk = hk / wk;
    float dy = yc - yk;
    float t2 = dk + dk1 - 2.f * sk;
    float qa = dy * t2 + hk * (sk - dk);
    float qb = hk * dk - dy * t2;
    float qc = -sk * dy;
    float disc = fmaxf(qb * qb - 4.f * qa * qc, 0.f);
    float theta = 2.f * qc / (-qb - sqrtf(disc));
    float xo = theta * wk + xk;
    float om = 1.f - theta;
    float denom = sk + t2 * theta * om;
    float dnum = sk * sk * (dk1 * theta * theta + 2.f * sk * theta * om + dk * om * om);
    float ldf = logf(dnum) - 2.f * logf(denom);
    xout  = inside ? xo : y;
    ldout = inside ? -ldf : 0.f;
}

// ------------------------------ setup kernels ------------------------------
// Transpose Wres -> [layer][gemm][k][n]; Wf rows [PM,2PM) -> [layer][k][24].
__global__ void transpose_kernel(const float* __restrict__ Wres,
                                 const float* __restrict__ Wf) {
    const int total1 = NLAYER * 4 * HDIM * HDIM;
    for (int t = blockIdx.x * blockDim.x + threadIdx.x; t < total1;
         t += gridDim.x * blockDim.x) {
        int n = t & 127;
        int k = (t >> 7) & 127;
        int base = t & ~16383;  // matrix base
        g_WresT[t] = Wres[base + n * HDIM + k];
    }
    const int total2 = NLAYER * HDIM * WFN;
    for (int t = blockIdx.x * blockDim.x + threadIdx.x; t < total2;
         t += gridDim.x * blockDim.x) {
        int m = t % WFN;
        int k = (t / WFN) % HDIM;
        int i = t / (WFN * HDIM);
        float v = 0.f;
        if (m < PMVAL) v = Wf[(i * (2 * PMVAL) + PMVAL + m) * HDIM + k];
        g_WfT[t] = v;
    }
}

// Per-layer constants: dim-0 spline tables (bias only), LU inverse, logdets.
__global__ void setup_kernel(const float* __restrict__ made_bf,
                             const float* __restrict__ lu_lower,
                             const float* __restrict__ lu_upper,
                             const float* __restrict__ lu_diag) {
    __shared__ float sldl[NLAYER];
    int i = threadIdx.x;
    if (i < NLAYER) {
        const float* bfL = made_bf + i * (2 * PMVAL);
        float uw[8], uh[8], ud[7];
        #pragma unroll
        for (int k = 0; k < 8; k++) {
            uw[k] = bfL[k] * INV_SQH;
            uh[k] = bfL[8 + k] * INV_SQH;
        }
        #pragma unroll
        for (int k = 0; k < 7; k++) ud[k] = bfL[16 + k];
        build_params(uw, uh, ud, g_cw0 + 9 * i, g_w0 + 8 * i,
                     g_ch0 + 9 * i, g_h0 + 8 * i, g_d0 + 9 * i);

        float l = lu_lower[i], u = lu_upper[i];
        float d0 = softplusf(lu_diag[2 * i]) + LUEPS;
        float d1 = softplusf(lu_diag[2 * i + 1]) + LUEPS;
        float invdet = 1.f / (d0 * d1);
        // Wm = [[d0, u],[l*d0, l*u+d1]]; inv = 1/det * [[l*u+d1, -u],[-l*d0, d0]]
        g_invW[4 * i + 0] = (l * u + d1) * invdet;
        g_invW[4 * i + 1] = -u * invdet;
        g_invW[4 * i + 2] = -l * d0 * invdet;
        g_invW[4 * i + 3] = d0 * invdet;
        sldl[i] = logf(d0) + logf(d1);
    }
    __syncthreads();
    if (i == 0) {
        float s = 0.f;
        for (int j = 0; j < NLAYER; j++) s += sldl[j];
        g_ldinit = -s;
    }
}

// ------------------------------ prelude ------------------------------------
__global__ void prelude_kernel(const float* __restrict__ z0in,
                               const float* __restrict__ xin,
                               const float* __restrict__ sigma,
                               const float* __restrict__ n1w1,
                               const float* __restrict__ n1b1,
                               const float* __restrict__ n1w2,
                               const float* __restrict__ n1b2,
                               const float* __restrict__ n2w1,
                               const float* __restrict__ n2b1,
                               const float* __restrict__ n2w2,
                               const float* __restrict__ n2b2) {
    __shared__ float s1w[32], s1b[32], s1o[64], s1ob[2];
    __shared__ float s2w[128], s2b[32], s2o[64], s2ob[2];
    __shared__ float sld;
    int tid = threadIdx.x;
    if (tid < 32) { s1w[tid] = n1w1[tid]; s1b[tid] = n1b1[tid]; s2b[tid] = n2b1[tid]; }
    if (tid < 64) { s1o[tid] = n1w2[tid]; s2o[tid] = n2w2[tid]; }
    if (tid < 128) s2w[tid] = n2w1[tid];
    if (tid < 2)  { s1ob[tid] = n1b2[tid]; s2ob[tid] = n2b2[tid]; }
    if (tid == 0) sld = g_ldinit;
    __syncthreads();

    int row = blockIdx.x * blockDim.x + tid;
    if (row >= BATCH) return;
    float sg = sigma[row];
    float a0 = z0in[2 * row], a1 = z0in[2 * row + 1];
    float b0v = xin[2 * row], b1v = xin[2 * row + 1];

    float t0 = s1ob[0], t1 = s1ob[1];
    #pragma unroll
    for (int j = 0; j < 32; j++) {
        float hv = s1w[j] * sg + s1b[j];
        hv = hv / (1.f + expf(-hv));        // silu
        t0 += s1o[j] * hv;
        t1 += s1o[32 + j] * hv;
    }
    float zc0 = s2ob[0], zc1 = s2ob[1];
    #pragma unroll
    for (int j = 0; j < 32; j++) {
        float hv = s2w[4 * j] * a0 + s2w[4 * j + 1] * a1
                 + s2w[4 * j + 2] * b0v + s2w[4 * j + 3] * b1v + s2b[j];
        hv = hv / (1.f + expf(-hv));
        zc0 += s2o[j] * hv;
        zc1 += s2o[32 + j] * hv;
    }
    g_state[2 * row]     = zc0 + t0;
    g_state[2 * row + 1] = zc1 + t1;
    g_ld[row] = sld;
}

// ------------------------------ layer kernel -------------------------------
// 128 rows per block, 256 threads, 8x8 register tiles.
// Smem (dynamic): Hs[128][132] feature-major h, Ts[128][132] t, Ws[128][132] W(k,n).
__global__ void __launch_bounds__(256, 1)
layer_kernel(int layer, int is_last,
             const float* __restrict__ made_W0,   // (16,128,2)
             const float* __restrict__ made_b0,   // (16,128)
             const float* __restrict__ made_bres, // (16,2,2,128)
             const float* __restrict__ made_bf,   // (16,46)
             const float* __restrict__ lu_bias,   // (16,2)
             const int*   __restrict__ perms,     // (16,2)
             float* __restrict__ out) {
    extern __shared__ float sm[];
    float* Hs = sm;
    float* Ts = sm + HDIM * LDA;
    float* Ws = sm + 2 * HDIM * LDA;

    __shared__ float s_cw0[9], s_w0[8], s_ch0[9], s_h0[8], s_d0[9];
    __shared__ float s_out0[HDIM];
    __shared__ float s_w0col[HDIM], s_b0[HDIM], s_bias[HDIM];
    __shared__ float s_invW[4], s_bias2[2];
    __shared__ int   s_perm[2];

    int tid = threadIdx.x;
    if (tid < 9) {
        s_cw0[tid] = g_cw0[9 * layer + tid];
        s_ch0[tid] = g_ch0[9 * layer + tid];
        s_d0[tid]  = g_d0[9 * layer + tid];
    }
    if (tid < 8) { s_w0[tid] = g_w0[8 * layer + tid]; s_h0[tid] = g_h0[8 * layer + tid]; }
    if (tid < 4) s_invW[tid] = g_invW[4 * layer + tid];
    if (tid < 2) { s_bias2[tid] = lu_bias[2 * layer + tid]; s_perm[tid] = perms[2 * layer + tid]; }
    if (tid < HDIM) {
        s_w0col[tid] = made_W0[(layer * HDIM + tid) * 2];   // masked col 0 only
        s_b0[tid]    = made_b0[layer * HDIM + tid];
    }
    __syncthreads();

    // Phase E1: dim-0 spline (constant params).
    float y1 = 0.f, ldp0 = 0.f, out0 = 0.f;
    int row = blockIdx.x * HDIM + tid;
    if (tid < HDIM) {
        float y0 = g_state[2 * row];
        y1 = g_state[2 * row + 1];
        rqs_inverse(y0, s_cw0, s_w0, s_ch0, s_h0, s_d0, out0, ldp0);
        s_out0[tid] = out0;
    }
    __syncthreads();

    // Fill Hs[c][r] = out0[r]*W0col[c] + b0[c]
    for (int t = tid; t < HDIM * HDIM; t += 256) {
        int c = t >> 7, r = t & 127;
        Hs[c * LDA + r] = s_out0[r] * s_w0col[c] + s_b0[c];
    }
    __syncthreads();

    int m0 = (tid & 15) * 8;
    int n0 = (tid >> 4) * 8;
    const float* WresTL = g_WresT + layer * 4 * HDIM * HDIM;
    const float* bresL  = made_bres + layer * 4 * HDIM;

    // 4 residual GEMMs: g even: Ts = relu(Hs)@W.T + b ; g odd: Hs += relu(Ts)@W.T + b
    for (int gg = 0; gg < 4; gg++) {
        const float* Wg = WresTL + gg * HDIM * HDIM;
        for (int t = tid; t < HDIM * 32; t += 256) {
            int k = t >> 5, v = (t & 31) << 2;
            float4 val = *reinterpret_cast<const float4*>(Wg + k * HDIM + v);
            *reinterpret_cast<float4*>(&Ws[k * LDA + v]) = val;
        }
        if (tid < HDIM) s_bias[tid] = bresL[gg * HDIM + tid];
        __syncthreads();

        const float* Asrc = (gg & 1) ? Ts : Hs;
        float acc[64];
        #pragma unroll
        for (int q = 0; q < 64; q++) acc[q] = 0.f;

        #pragma unroll 4
        for (int k = 0; k < HDIM; k++) {
            const float* arow = Asrc + k * LDA;
            float4 av0 = *reinterpret_cast<const float4*>(arow + m0);
            float4 av1 = *reinterpret_cast<const float4*>(arow + m0 + 4);
            float a[8];
            a[0] = fmaxf(av0.x, 0.f); a[1] = fmaxf(av0.y, 0.f);
            a[2] = fmaxf(av0.z, 0.f); a[3] = fmaxf(av0.w, 0.f);
            a[4] = fmaxf(av1.x, 0.f); a[5] = fmaxf(av1.y, 0.f);
            a[6] = fmaxf(av1.z, 0.f); a[7] = fmaxf(av1.w, 0.f);
            const float* brow = Ws + k * LDA;
            float4 bv0 = *reinterpret_cast<const float4*>(brow + n0);
            float4 bv1 = *reinterpret_cast<const float4*>(brow + n0 + 4);
            float bb[8] = {bv0.x, bv0.y, bv0.z, bv0.w, bv1.x, bv1.y, bv1.z, bv1.w};
            #pragma unroll
            for (int jn = 0; jn < 8; jn++)
                #pragma unroll
                for (int jm = 0; jm < 8; jm++)
                    acc[jn * 8 + jm] = fmaf(a[jm], bb[jn], acc[jn * 8 + jm]);
        }

        if (gg & 1) {
            #pragma unroll
            for (int jn = 0; jn < 8; jn++) {
                float bv = s_bias[n0 + jn];
                #pragma unroll
                for (int jm = 0; jm < 8; jm++)
                    Hs[(n0 + jn) * LDA + m0 + jm] += acc[jn * 8 + jm] + bv;
            }
        } else {
            #pragma unroll
            for (int jn = 0; jn < 8; jn++) {
                float bv = s_bias[n0 + jn];
                #pragma unroll
                for (int jm = 0; jm < 8; jm++)
                    Ts[(n0 + jn) * LDA + m0 + jm] = acc[jn * 8 + jm] + bv;
            }
        }
        __syncthreads();
    }

    // GEMM5: p1[r][m] = sum_k Hs[k][r] * WfT[k][m]   (raw h, no relu)
    for (int t = tid; t < HDIM * WFN; t += 256)
        Ws[t] = g_WfT[layer * HDIM * WFN + t];
    __syncthreads();
    {
        int r = tid >> 1;
        int mbase = (tid & 1) * 12;
        float accp[12];
        #pragma unroll
        for (int j = 0; j < 12; j++) accp[j] = 0.f;
        for (int k = 0; k < HDIM; k++) {
            float hv = Hs[k * LDA + r];
            const float* wrow = Ws + k * WFN + mbase;
            #pragma unroll
            for (int j = 0; j < 12; j++) accp[j] = fmaf(hv, wrow[j], accp[j]);
        }
        #pragma unroll
        for (int j = 0; j < 12; j++) Ts[r * WFN + mbase + j] = accp[j];
    }
    __syncthreads();

    // Phase E2: dim-1 spline + LU + permutation.
    if (tid < HDIM) {
        const float* bf1 = made_bf + layer * (2 * PMVAL) + PMVAL;
        float p1[PMVAL];
        #pragma unroll
        for (int m = 0; m < PMVAL; m++) p1[m] = Ts[tid * WFN + m] + bf1[m];
        float uw[8], uh[8], ud[7];
        #pragma unroll
        for (int k = 0; k < 8; k++) { uw[k] = p1[k] * INV_SQH; uh[k] = p1[8 + k] * INV_SQH; }
        #pragma unroll
        for (int k = 0; k < 7; k++) ud[k] = p1[16 + k];
        float cw[9], ww[8], chh[9], hh2[8], dd[9];
        build_params(uw, uh, ud, cw, ww, chh, hh2, dd);
        float out1, ldp1;
        rqs_inverse(y1, cw, ww, chh, hh2, dd, out1, ldp1);

        float ld = g_ld[row] + ldp0 + ldp1;
        float v0 = out0 - s_bias2[0];
        float v1 = out1 - s_bias2[1];
        float zz[2];
        zz[0] = s_invW[0] * v0 + s_invW[1] * v1;
        zz[1] = s_invW[2] * v0 + s_invW[3] * v1;
        float ny0 = zz[s_perm[0]];
        float ny1 = zz[s_perm[1]];
        if (is_last) {
            out[2 * row]     = ny0;
            out[2 * row + 1] = ny1;
            out[2 * BATCH + row] = ld;
        } else {
            g_state[2 * row]     = ny0;
            g_state[2 * row + 1] = ny1;
            g_ld[row] = ld;
        }
    }
}

// ------------------------------ launcher -----------------------------------
extern "C" void kernel_launch(void* const* d_in, const int* in_sizes, int n_in,
                              void* d_out, int out_size) {
    const float* z0      = (const float*)d_in[0];
    const float* x       = (const float*)d_in[1];
    const float* sigma   = (const float*)d_in[2];
    const float* n1_w1   = (const float*)d_in[3];
    const float* n1_b1   = (const float*)d_in[4];
    const float* n1_w2   = (const float*)d_in[5];
    const float* n1_b2   = (const float*)d_in[6];
    const float* n2_w1   = (const float*)d_in[7];
    const float* n2_b1   = (const float*)d_in[8];
    const float* n2_w2   = (const float*)d_in[9];
    const float* n2_b2   = (const float*)d_in[10];
    const float* made_W0 = (const float*)d_in[11];
    const float* made_b0 = (const float*)d_in[12];
    const float* made_Wres = (const float*)d_in[13];
    const float* made_bres = (const float*)d_in[14];
    const float* made_Wf   = (const float*)d_in[15];
    const float* made_bf   = (const float*)d_in[16];
    const float* lu_lower  = (const float*)d_in[17];
    const float* lu_upper  = (const float*)d_in[18];
    const float* lu_diag   = (const float*)d_in[19];
    const float* lu_bias   = (const float*)d_in[20];
    const int*   perms     = (const int*)d_in[21];
    float* out = (float*)d_out;

    cudaFuncSetAttribute(layer_kernel,
                         cudaFuncAttributeMaxDynamicSharedMemorySize, SMEM_BYTES);

    transpose_kernel<<<4096, 256>>>(made_Wres, made_Wf);
    setup_kernel<<<1, 32>>>(made_bf, lu_lower, lu_upper, lu_diag);
    prelude_kernel<<<BATCH / 256, 256>>>(z0, x, sigma, n1_w1, n1_b1, n1_w2, n1_b2,
                                         n2_w1, n2_b1, n2_w2, n2_b2);
    for (int i = 0; i < NLAYER; i++) {
        layer_kernel<<<BATCH / HDIM, 256, SMEM_BYTES>>>(
            i, (i == NLAYER - 1) ? 1 : 0,
            made_W0, made_b0, made_bres, made_bf, lu_bias, perms, out);
    }
    (void)in_sizes; (void)n_in; (void)out_size;
}

// round 3
// speedup vs baseline: 2.4068x; 2.4068x over previous
#include <cuda_runtime.h>
#include <cuda_bf16.h>
#include <math.h>
#include <stdint.h>

// ---------------------------------------------------------------------------
// NeuralSplineFlow forward — mma.sync (bf16 hi/lo split, fp32 accum) version.
// tcgen05 is unavailable at this harness's PTX target (compute_103), so GEMMs
// use Ampere-class m16n8k16 bf16 mma.sync + ldmatrix + cp.async, which are
// target-portable and run on the tensor pipe.
//
// Per layer: out0 = const-spline(y0); h = out0*W0col + b0; 2 residual blocks
// (4x [128x128] GEMM); p1 = h @ Wf^T (N=24); spline(y1; p1); 2x2 LU; perm.
// fp32 emulated as 3 bf16 products: Ah*Bh + Al*Bh + Ah*Bl (~2e-5 rel).
// ---------------------------------------------------------------------------

#define BATCH   262144
#define NLAYER  16
#define HDIM    128
#define NBINS   8
#define PMVAL   23
#define TBV     3.0f
#define MINWV   0.001f
#define MINDV   0.001f
#define LUEPS   0.001f
#define INV_SQH 0.08838834764831843f   // 1/sqrt(128)

// SMEM geometry
#define KSTRIDE   136                    // bf16 per row (pad 128 -> 136)
#define ROWB      (KSTRIDE * 2)          // 272 bytes per row
#define ACT_BYTES (HDIM * ROWB)          // 34816
#define WMAT_ELEMS (HDIM * KSTRIDE)      // 17408 bf16 per matrix half
#define WSLOT_BYTES (2 * ACT_BYTES)      // hi+lo = 69632
#define WF_STRIDE 40                     // bf16 per row for Wf image
#define WF_HALF   (HDIM * WF_STRIDE)     // 5120 elems per half
#define WF_BYTES  (2 * WF_HALF * 2)      // 20480 bytes

// dynamic smem layout
#define OFF_ACTHI 0
#define OFF_ACTLO 34816
#define OFF_SLOT0 69632
#define OFF_SLOT1 139264
#define OFF_P1    139264                 // reuse slot1 after last res-GEMM
#define DYN_SMEM  208896

// ----------------------------- device scratch ------------------------------
__device__ float g_state[BATCH * 2];
__device__ float g_ld[BATCH];
// weight images: per (layer,gemm): [hi 128x136][lo 128x136] bf16, [k][n], padded
__device__ __align__(16) uint16_t g_Wimg[NLAYER * 4 * 2 * WMAT_ELEMS];
// Wf images: per layer: [hi 128x40][lo 128x40] bf16, [k][n], n<23 real
__device__ __align__(16) uint16_t g_Wfimg[NLAYER * 2 * WF_HALF];
__device__ float g_cw0[NLAYER * 9];
__device__ float g_w0[NLAYER * 8];
__device__ float g_ch0[NLAYER * 9];
__device__ float g_h0[NLAYER * 8];
__device__ float g_d0[NLAYER * 9];
__device__ float g_invW[NLAYER * 4];
__device__ float g_ldinit;

// ----------------------------- PTX helpers ---------------------------------
__device__ __forceinline__ uint32_t smem_u32(const void* p) {
    uint32_t a;
    asm("{ .reg .u64 t; cvta.to.shared.u64 t, %1; cvt.u32.u64 %0, t; }"
        : "=r"(a) : "l"(p));
    return a;
}
__device__ __forceinline__ void ldmA4(uint32_t a[4], uint32_t addr) {
    asm volatile("ldmatrix.sync.aligned.m8n8.x4.shared.b16 {%0,%1,%2,%3}, [%4];"
        : "=r"(a[0]), "=r"(a[1]), "=r"(a[2]), "=r"(a[3]) : "r"(addr));
}
__device__ __forceinline__ void ldmB4t(uint32_t b[4], uint32_t addr) {
    asm volatile("ldmatrix.sync.aligned.m8n8.x4.trans.shared.b16 {%0,%1,%2,%3}, [%4];"
        : "=r"(b[0]), "=r"(b[1]), "=r"(b[2]), "=r"(b[3]) : "r"(addr));
}
__device__ __forceinline__ void mmabf(float d[4], const uint32_t a[4],
                                      uint32_t b0, uint32_t b1) {
    asm volatile("mma.sync.aligned.m16n8k16.row.col.f32.bf16.bf16.f32 "
        "{%0,%1,%2,%3}, {%4,%5,%6,%7}, {%8,%9}, {%0,%1,%2,%3};"
        : "+f"(d[0]), "+f"(d[1]), "+f"(d[2]), "+f"(d[3])
        : "r"(a[0]), "r"(a[1]), "r"(a[2]), "r"(a[3]), "r"(b0), "r"(b1));
}
__device__ __forceinline__ void cpasync16(uint32_t dst, const void* src) {
    asm volatile("cp.async.cg.shared.global [%0], [%1], 16;"
                 :: "r"(dst), "l"(src));
}
#define CP_COMMIT() asm volatile("cp.async.commit_group;" ::: "memory")
#define CP_WAIT0()  asm volatile("cp.async.wait_group 0;" ::: "memory")

// ----------------------------- math helpers --------------------------------
__device__ __forceinline__ float softplusf(float x) {
    return fmaxf(x, 0.f) + log1pf(expf(-fabsf(x)));
}

__device__ void build_params(const float* uw, const float* uh, const float* ud,
                             float* cw, float* w, float* ch, float* hh, float* dd) {
    {
        float mx = uw[0];
        #pragma unroll
        for (int k = 1; k < NBINS; k++) mx = fmaxf(mx, uw[k]);
        float e[NBINS]; float s = 0.f;
        #pragma unroll
        for (int k = 0; k < NBINS; k++) { e[k] = expf(uw[k] - mx); s += e[k]; }
        float inv = 1.f / s;
        cw[0] = -TBV; float cum = 0.f;
        #pragma unroll
        for (int k = 0; k < NBINS; k++) {
            float wk = MINWV + (1.f - MINWV * NBINS) * e[k] * inv;
            cum += wk;
            cw[k + 1] = 2.f * TBV * cum - TBV;
        }
        cw[NBINS] = TBV;
        #pragma unroll
        for (int k = 0; k < NBINS; k++) w[k] = cw[k + 1] - cw[k];
    }
    {
        float mx = uh[0];
        #pragma unroll
        for (int k = 1; k < NBINS; k++) mx = fmaxf(mx, uh[k]);
        float e[NBINS]; float s = 0.f;
        #pragma unroll
        for (int k = 0; k < NBINS; k++) { e[k] = expf(uh[k] - mx); s += e[k]; }
        float inv = 1.f / s;
        ch[0] = -TBV; float cum = 0.f;
        #pragma unroll
        for (int k = 0; k < NBINS; k++) {
            float hk = MINWV + (1.f - MINWV * NBINS) * e[k] * inv;
            cum += hk;
            ch[k + 1] = 2.f * TBV * cum - TBV;
        }
        ch[NBINS] = TBV;
        #pragma unroll
        for (int k = 0; k < NBINS; k++) hh[k] = ch[k + 1] - ch[k];
    }
    dd[0] = 1.0f;
    #pragma unroll
    for (int k = 0; k < 7; k++) dd[k + 1] = MINDV + softplusf(ud[k]);
    dd[NBINS] = 1.0f;
}

__device__ void rqs_inverse(float y, const float* cw, const float* w,
                            const float* ch, const float* hh, const float* dd,
                            float& xout, float& ldout) {
    bool inside = (y >= -TBV) && (y <= TBV);
    float yc = fminf(fmaxf(y, -TBV), TBV);
    int idx = 0;
    #pragma unroll
    for (int k = 1; k <= NBINS; k++) idx += (yc >= ch[k]) ? 1 : 0;
    idx = min(idx, NBINS - 1);
    float yk = ch[idx], hk = hh[idx], xk = cw[idx], wk = w[idx];
    float dk = dd[idx], dk1 = dd[idx + 1];
    float sk = hk / wk;
    float dy = yc - yk;
    float t2 = dk + dk1 - 2.f * sk;
    float qa = dy * t2 + hk * (sk - dk);
    float qb = hk * dk - dy * t2;
    float qc = -sk * dy;
    float disc = fmaxf(qb * qb - 4.f * qa * qc, 0.f);
    float theta = 2.f * qc / (-qb - sqrtf(disc));
    float xo = theta * wk + xk;
    float om = 1.f - theta;
    float denom = sk + t2 * theta * om;
    float dnum = sk * sk * (dk1 * theta * theta + 2.f * sk * theta * om + dk * om * om);
    float ldf = logf(dnum) - 2.f * logf(denom);
    xout  = inside ? xo : y;
    ldout = inside ? -ldf : 0.f;
}

__device__ __forceinline__ void split2(float a, float b, uint32_t& hi, uint32_t& lo) {
    __nv_bfloat16 ah = __float2bfloat16(a), bh = __float2bfloat16(b);
    __nv_bfloat16 al = __float2bfloat16(a - __bfloat162float(ah));
    __nv_bfloat16 bl = __float2bfloat16(b - __bfloat162float(bh));
    hi = (uint32_t)__bfloat16_as_ushort(ah) | ((uint32_t)__bfloat16_as_ushort(bh) << 16);
    lo = (uint32_t)__bfloat16_as_ushort(al) | ((uint32_t)__bfloat16_as_ushort(bl) << 16);
}

// ------------------------------ setup kernels ------------------------------
__global__ void build_wimg_kernel(const float* __restrict__ Wres,
                                  const float* __restrict__ Wf) {
    // residual weights: B[k][n] = Wres[n][k], padded to KSTRIDE cols
    const int total1 = NLAYER * 4 * HDIM * KSTRIDE;
    for (int t = blockIdx.x * blockDim.x + threadIdx.x; t < total1;
         t += gridDim.x * blockDim.x) {
        int n  = t % KSTRIDE;
        int k  = (t / KSTRIDE) % HDIM;
        int mg = t / (KSTRIDE * HDIM);
        float v = (n < HDIM) ? Wres[mg * 16384 + n * HDIM + k] : 0.f;
        __nv_bfloat16 h = __float2bfloat16(v);
        __nv_bfloat16 l = __float2bfloat16(v - __bfloat162float(h));
        int base = (mg * 2) * WMAT_ELEMS + k * KSTRIDE + n;
        g_Wimg[base]              = __bfloat16_as_ushort(h);
        g_Wimg[base + WMAT_ELEMS] = __bfloat16_as_ushort(l);
    }
    // Wf: B[k][n] = Wf[layer][PM + n][k], n<23, pad to 40
    const int total2 = NLAYER * HDIM * WF_STRIDE;
    for (int t = blockIdx.x * blockDim.x + threadIdx.x; t < total2;
         t += gridDim.x * blockDim.x) {
        int n  = t % WF_STRIDE;
        int k  = (t / WF_STRIDE) % HDIM;
        int ly = t / (WF_STRIDE * HDIM);
        float v = (n < PMVAL) ? Wf[(ly * (2 * PMVAL) + PMVAL + n) * HDIM + k] : 0.f;
        __nv_bfloat16 h = __float2bfloat16(v);
        __nv_bfloat16 l = __float2bfloat16(v - __bfloat162float(h));
        int base = (ly * 2) * WF_HALF + k * WF_STRIDE + n;
        g_Wfimg[base]           = __bfloat16_as_ushort(h);
        g_Wfimg[base + WF_HALF] = __bfloat16_as_ushort(l);
    }
}

__global__ void setup_kernel(const float* __restrict__ made_bf,
                             const float* __restrict__ lu_lower,
                             const float* __restrict__ lu_upper,
                             const float* __restrict__ lu_diag) {
    __shared__ float sldl[NLAYER];
    int i = threadIdx.x;
    if (i < NLAYER) {
        const float* bfL = made_bf + i * (2 * PMVAL);
        float uw[8], uh[8], ud[7];
        #pragma unroll
        for (int k = 0; k < 8; k++) { uw[k] = bfL[k] * INV_SQH; uh[k] = bfL[8 + k] * INV_SQH; }
        #pragma unroll
        for (int k = 0; k < 7; k++) ud[k] = bfL[16 + k];
        build_params(uw, uh, ud, g_cw0 + 9 * i, g_w0 + 8 * i,
                     g_ch0 + 9 * i, g_h0 + 8 * i, g_d0 + 9 * i);
        float l = lu_lower[i], u = lu_upper[i];
        float d0 = softplusf(lu_diag[2 * i]) + LUEPS;
        float d1 = softplusf(lu_diag[2 * i + 1]) + LUEPS;
        float invdet = 1.f / (d0 * d1);
        g_invW[4 * i + 0] = (l * u + d1) * invdet;
        g_invW[4 * i + 1] = -u * invdet;
        g_invW[4 * i + 2] = -l * d0 * invdet;
        g_invW[4 * i + 3] = d0 * invdet;
        sldl[i] = logf(d0) + logf(d1);
    }
    __syncthreads();
    if (i == 0) {
        float s = 0.f;
        for (int j = 0; j < NLAYER; j++) s += sldl[j];
        g_ldinit = -s;
    }
}

// ------------------------------ prelude ------------------------------------
__global__ void prelude_kernel(const float* __restrict__ z0in,
                               const float* __restrict__ xin,
                               const float* __restrict__ sigma,
                               const float* __restrict__ n1w1,
                               const float* __restrict__ n1b1,
                               const float* __restrict__ n1w2,
                               const float* __restrict__ n1b2,
                               const float* __restrict__ n2w1,
                               const float* __restrict__ n2b1,
                               const float* __restrict__ n2w2,
                               const float* __restrict__ n2b2) {
    __shared__ float s1w[32], s1b[32], s1o[64], s1ob[2];
    __shared__ float s2w[128], s2b[32], s2o[64], s2ob[2];
    __shared__ float sld;
    int tid = threadIdx.x;
    if (tid < 32) { s1w[tid] = n1w1[tid]; s1b[tid] = n1b1[tid]; s2b[tid] = n2b1[tid]; }
    if (tid < 64) { s1o[tid] = n1w2[tid]; s2o[tid] = n2w2[tid]; }
    if (tid < 128) s2w[tid] = n2w1[tid];
    if (tid < 2)  { s1ob[tid] = n1b2[tid]; s2ob[tid] = n2b2[tid]; }
    if (tid == 0) sld = g_ldinit;
    __syncthreads();

    int row = blockIdx.x * blockDim.x + tid;
    if (row >= BATCH) return;
    float sg = sigma[row];
    float a0 = z0in[2 * row], a1 = z0in[2 * row + 1];
    float b0v = xin[2 * row], b1v = xin[2 * row + 1];
    float t0 = s1ob[0], t1 = s1ob[1];
    #pragma unroll
    for (int j = 0; j < 32; j++) {
        float hv = s1w[j] * sg + s1b[j];
        hv = hv / (1.f + expf(-hv));
        t0 += s1o[j] * hv;
        t1 += s1o[32 + j] * hv;
    }
    float zc0 = s2ob[0], zc1 = s2ob[1];
    #pragma unroll
    for (int j = 0; j < 32; j++) {
        float hv = s2w[4 * j] * a0 + s2w[4 * j + 1] * a1
                 + s2w[4 * j + 2] * b0v + s2w[4 * j + 3] * b1v + s2b[j];
        hv = hv / (1.f + expf(-hv));
        zc0 += s2o[j] * hv;
        zc1 += s2o[32 + j] * hv;
    }
    g_state[2 * row]     = zc0 + t0;
    g_state[2 * row + 1] = zc1 + t1;
    g_ld[row] = sld;
}

// ------------------------------ layer kernel -------------------------------
__device__ __forceinline__ void prefetch_w(uint32_t dst_u, const uint16_t* gsrc,
                                           int chunks, int tid) {
    const char* s = (const char*)gsrc;
    for (int i = tid; i < chunks; i += 256)
        cpasync16(dst_u + i * 16, s + i * 16);
    CP_COMMIT();
}

__global__ void __launch_bounds__(256, 1)
layer_kernel(int layer, int is_last,
             const float* __restrict__ made_W0,   // (16,128,2)
             const float* __restrict__ made_b0,   // (16,128)
             const float* __restrict__ made_bres, // (16,2,2,128)
             const float* __restrict__ made_bf,   // (16,46)
             const float* __restrict__ lu_bias,   // (16,2)
             const int*   __restrict__ perms,     // (16,2)
             float* __restrict__ out) {
    extern __shared__ char dynsm[];
    __shared__ float s_bias[4][HDIM];
    __shared__ float s_out0[HDIM];
    __shared__ float s_w0col[HDIM], s_b0[HDIM];
    __shared__ float s_cw0[9], s_ch0[9], s_d0[9], s_w0s[8], s_h0s[8];
    __shared__ float s_invW[4], s_bias2[2];
    __shared__ int   s_perm[2];

    const int tid  = threadIdx.x;
    const int lane = tid & 31;
    const int w    = tid >> 5;

    const uint32_t base_u  = smem_u32(dynsm);
    const uint32_t actHi_u = base_u + OFF_ACTHI;
    const uint32_t actLo_u = base_u + OFF_ACTLO;
    const uint32_t slot_u[2] = { base_u + OFF_SLOT0, base_u + OFF_SLOT1 };

    // prefetch gemm0 weights
    prefetch_w(slot_u[0], g_Wimg + (size_t)(layer * 4) * (2 * WMAT_ELEMS),
               WSLOT_BYTES / 16, tid);

    // constants
    if (tid < 9) { s_cw0[tid] = g_cw0[9 * layer + tid];
                   s_ch0[tid] = g_ch0[9 * layer + tid];
                   s_d0[tid]  = g_d0[9 * layer + tid]; }
    if (tid < 8) { s_w0s[tid] = g_w0[8 * layer + tid];
                   s_h0s[tid] = g_h0[8 * layer + tid]; }
    if (tid < 4) s_invW[tid] = g_invW[4 * layer + tid];
    if (tid < 2) { s_bias2[tid] = lu_bias[2 * layer + tid];
                   s_perm[tid]  = perms[2 * layer + tid]; }
    if (tid < HDIM) {
        s_w0col[tid] = made_W0[(layer * HDIM + tid) * 2];
        s_b0[tid]    = made_b0[layer * HDIM + tid];
    }
    for (int i = tid; i < 4 * HDIM; i += 256)
        s_bias[i >> 7][i & 127] = made_bres[layer * 4 * HDIM + i];
    __syncthreads();

    // ---- Phase E1: dim-0 spline (threads 0-127, row = tid) ----
    float y1 = 0.f, out0 = 0.f, ldp0 = 0.f;
    const int rowE = blockIdx.x * HDIM + (tid < HDIM ? tid : 0);
    if (tid < HDIM) {
        float y0 = g_state[2 * rowE];
        y1 = g_state[2 * rowE + 1];
        rqs_inverse(y0, s_cw0, s_w0s, s_ch0, s_h0s, s_d0, out0, ldp0);
        s_out0[tid] = out0;
    }
    __syncthreads();

    // ---- fill H (D-fragment layout) + act ----
    const int r0 = w * 16 + (lane >> 2);
    const int r1 = r0 + 8;
    const int cB = (lane & 3) * 2;
    const uint32_t o0 = (uint32_t)r0 * ROWB + cB * 2;
    const uint32_t o1 = (uint32_t)r1 * ROWB + cB * 2;

    float H[64];
    {
        float oa = s_out0[r0], ob = s_out0[r1];
        #pragma unroll
        for (int t = 0; t < 16; t++) {
            int c = t * 8 + cB;
            float2 wc = *(const float2*)&s_w0col[c];
            float2 bc = *(const float2*)&s_b0[c];
            float h0 = fmaf(oa, wc.x, bc.x), h1 = fmaf(oa, wc.y, bc.y);
            float h2 = fmaf(ob, wc.x, bc.x), h3 = fmaf(ob, wc.y, bc.y);
            H[t * 4] = h0; H[t * 4 + 1] = h1; H[t * 4 + 2] = h2; H[t * 4 + 3] = h3;
            uint32_t hi0, lo0, hi1, lo1;
            split2(fmaxf(h0, 0.f), fmaxf(h1, 0.f), hi0, lo0);
            split2(fmaxf(h2, 0.f), fmaxf(h3, 0.f), hi1, lo1);
            *(uint32_t*)(dynsm + OFF_ACTHI + o0 + t * 16) = hi0;
            *(uint32_t*)(dynsm + OFF_ACTHI + o1 + t * 16) = hi1;
            *(uint32_t*)(dynsm + OFF_ACTLO + o0 + t * 16) = lo0;
            *(uint32_t*)(dynsm + OFF_ACTLO + o1 + t * 16) = lo1;
        }
    }
    CP_WAIT0();
    __syncthreads();   // act ready + slot0 ready

    // ldmatrix bases
    const uint32_t aHiBase = actHi_u + (uint32_t)(w * 16 + (lane & 15)) * ROWB
                             + ((lane >> 4) * 16);
    const uint32_t aLoBase = aHiBase + ACT_BYTES;
    const uint32_t bOff    = (uint32_t)(lane & 15) * ROWB + ((lane >> 4) * 16);
    const uint32_t wfOff   = (uint32_t)(lane & 15) * (WF_STRIDE * 2) + ((lane >> 4) * 16);

    // ---- 4 residual GEMMs ----
    #pragma unroll 1
    for (int g = 0; g < 4; g++) {
        if (g < 3)
            prefetch_w(slot_u[(g + 1) & 1],
                       g_Wimg + (size_t)(layer * 4 + g + 1) * (2 * WMAT_ELEMS),
                       WSLOT_BYTES / 16, tid);
        else
            prefetch_w(slot_u[0], g_Wfimg + (size_t)layer * (2 * WF_HALF),
                       WF_BYTES / 16, tid);

        __syncwarp();
        uint32_t Ah[8][4], Al[8][4];
        #pragma unroll
        for (int kc = 0; kc < 8; kc++) {
            ldmA4(Ah[kc], aHiBase + kc * 32);
            ldmA4(Al[kc], aLoBase + kc * 32);
        }
        const uint32_t wbase = slot_u[g & 1] + bOff;

        #pragma unroll
        for (int tp = 0; tp < 8; tp++) {
            float D0[4] = {0.f, 0.f, 0.f, 0.f};
            float D1[4] = {0.f, 0.f, 0.f, 0.f};
            #pragma unroll
            for (int kc = 0; kc < 8; kc++) {
                uint32_t bh[4], bl[4];
                ldmB4t(bh, wbase + kc * (16 * ROWB) + tp * 32);
                ldmB4t(bl, wbase + ACT_BYTES + kc * (16 * ROWB) + tp * 32);
                mmabf(D0, Ah[kc], bh[0], bh[1]);
                mmabf(D0, Al[kc], bh[0], bh[1]);
                mmabf(D0, Ah[kc], bl[0], bl[1]);
                mmabf(D1, Ah[kc], bh[2], bh[3]);
                mmabf(D1, Al[kc], bh[2], bh[3]);
                mmabf(D1, Ah[kc], bl[2], bl[3]);
            }
            // epilogue for tiles t = 2*tp, 2*tp+1
            #pragma unroll
            for (int q = 0; q < 2; q++) {
                const int t = tp * 2 + q;
                float* D = q ? D1 : D0;
                float2 bb = *(const float2*)&s_bias[g][t * 8 + cB];
                float v0, v1, v2, v3;
                if ((g & 1) == 0) {
                    v0 = fmaxf(D[0] + bb.x, 0.f);
                    v1 = fmaxf(D[1] + bb.y, 0.f);
                    v2 = fmaxf(D[2] + bb.x, 0.f);
                    v3 = fmaxf(D[3] + bb.y, 0.f);
                } else {
                    float n0 = H[t * 4]     + D[0] + bb.x;
                    float n1 = H[t * 4 + 1] + D[1] + bb.y;
                    float n2 = H[t * 4 + 2] + D[2] + bb.x;
                    float n3 = H[t * 4 + 3] + D[3] + bb.y;
                    H[t * 4] = n0; H[t * 4 + 1] = n1;
                    H[t * 4 + 2] = n2; H[t * 4 + 3] = n3;
                    if (g == 3) { v0 = n0; v1 = n1; v2 = n2; v3 = n3; }
                    else { v0 = fmaxf(n0, 0.f); v1 = fmaxf(n1, 0.f);
                           v2 = fmaxf(n2, 0.f); v3 = fmaxf(n3, 0.f); }
                }
                uint32_t hi0, lo0, hi1, lo1;
                split2(v0, v1, hi0, lo0);
                split2(v2, v3, hi1, lo1);
                *(uint32_t*)(dynsm + OFF_ACTHI + o0 + t * 16) = hi0;
                *(uint32_t*)(dynsm + OFF_ACTHI + o1 + t * 16) = hi1;
                *(uint32_t*)(dynsm + OFF_ACTLO + o0 + t * 16) = lo0;
                *(uint32_t*)(dynsm + OFF_ACTLO + o1 + t * 16) = lo1;
            }
        }
        CP_WAIT0();
        __syncthreads();
    }

    // ---- Wf GEMM: p1 = h @ Wf^T (24 cols, 4 tiles computed, last is pad) ----
    {
        __syncwarp();
        uint32_t Ah[8][4], Al[8][4];
        #pragma unroll
        for (int kc = 0; kc < 8; kc++) {
            ldmA4(Ah[kc], aHiBase + kc * 32);
            ldmA4(Al[kc], aLoBase + kc * 32);
        }
        const uint32_t wfb = slot_u[0] + wfOff;
        float* p1 = (float*)(dynsm + OFF_P1);
        #pragma unroll
        for (int tp = 0; tp < 2; tp++) {
            float D0[4] = {0.f, 0.f, 0.f, 0.f};
            float D1[4] = {0.f, 0.f, 0.f, 0.f};
            #pragma unroll
            for (int kc = 0; kc < 8; kc++) {
                uint32_t bh[4], bl[4];
                ldmB4t(bh, wfb + kc * (16 * WF_STRIDE * 2) + tp * 32);
                ldmB4t(bl, wfb + 2 * WF_HALF + kc * (16 * WF_STRIDE * 2) + tp * 32);
                mmabf(D0, Ah[kc], bh[0], bh[1]);
                mmabf(D0, Al[kc], bh[0], bh[1]);
                mmabf(D0, Ah[kc], bl[0], bl[1]);
                mmabf(D1, Ah[kc], bh[2], bh[3]);
                mmabf(D1, Al[kc], bh[2], bh[3]);
                mmabf(D1, Ah[kc], bl[2], bl[3]);
            }
            int c0 = tp * 16 + cB;
            p1[r0 * 26 + c0] = D0[0]; p1[r0 * 26 + c0 + 1] = D0[1];
            p1[r1 * 26 + c0] = D0[2]; p1[r1 * 26 + c0 + 1] = D0[3];
            if (tp == 0) {
                p1[r0 * 26 + c0 + 8] = D1[0]; p1[r0 * 26 + c0 + 9] = D1[1];
                p1[r1 * 26 + c0 + 8] = D1[2]; p1[r1 * 26 + c0 + 9] = D1[3];
            }
        }
    }
    __syncthreads();

    // ---- Phase E2: dim-1 spline + LU + permutation (threads 0-127) ----
    if (tid < HDIM) {
        const float* p1r = (const float*)(dynsm + OFF_P1) + tid * 26;
        const float* bf1 = made_bf + layer * (2 * PMVAL) + PMVAL;
        float uw[8], uh[8], ud[7];
        #pragma unroll
        for (int k = 0; k < 8; k++) {
            uw[k] = (p1r[k]     + bf1[k])     * INV_SQH;
            uh[k] = (p1r[8 + k] + bf1[8 + k]) * INV_SQH;
        }
        #pragma unroll
        for (int k = 0; k < 7; k++) ud[k] = p1r[16 + k] + bf1[16 + k];
        float cw[9], ww[8], chh[9], hh2[8], dd[9];
        build_params(uw, uh, ud, cw, ww, chh, hh2, dd);
        float out1, ldp1;
        rqs_inverse(y1, cw, ww, chh, hh2, dd, out1, ldp1);

        float ld = g_ld[rowE] + ldp0 + ldp1;
        float v0 = out0 - s_bias2[0];
        float v1 = out1 - s_bias2[1];
        float zz[2];
        zz[0] = s_invW[0] * v0 + s_invW[1] * v1;
        zz[1] = s_invW[2] * v0 + s_invW[3] * v1;
        float ny0 = zz[s_perm[0]];
        float ny1 = zz[s_perm[1]];
        if (is_last) {
            out[2 * rowE]         = ny0;
            out[2 * rowE + 1]     = ny1;
            out[2 * BATCH + rowE] = ld;
        } else {
            g_state[2 * rowE]     = ny0;
            g_state[2 * rowE + 1] = ny1;
            g_ld[rowE] = ld;
        }
    }
}

// ------------------------------ launcher -----------------------------------
extern "C" void kernel_launch(void* const* d_in, const int* in_sizes, int n_in,
                              void* d_out, int out_size) {
    const float* z0      = (const float*)d_in[0];
    const float* x       = (const float*)d_in[1];
    const float* sigma   = (const float*)d_in[2];
    const float* n1_w1   = (const float*)d_in[3];
    const float* n1_b1   = (const float*)d_in[4];
    const float* n1_w2   = (const float*)d_in[5];
    const float* n1_b2   = (const float*)d_in[6];
    const float* n2_w1   = (const float*)d_in[7];
    const float* n2_b1   = (const float*)d_in[8];
    const float* n2_w2   = (const float*)d_in[9];
    const float* n2_b2   = (const float*)d_in[10];
    const float* made_W0 = (const float*)d_in[11];
    const float* made_b0 = (const float*)d_in[12];
    const float* made_Wres = (const float*)d_in[13];
    const float* made_bres = (const float*)d_in[14];
    const float* made_Wf   = (const float*)d_in[15];
    const float* made_bf   = (const float*)d_in[16];
    const float* lu_lower  = (const float*)d_in[17];
    const float* lu_upper  = (const float*)d_in[18];
    const float* lu_diag   = (const float*)d_in[19];
    const float* lu_bias   = (const float*)d_in[20];
    const int*   perms     = (const int*)d_in[21];
    float* out = (float*)d_out;

    cudaFuncSetAttribute(layer_kernel,
                         cudaFuncAttributeMaxDynamicSharedMemorySize, DYN_SMEM);

    build_wimg_kernel<<<2048, 256>>>(made_Wres, made_Wf);
    setup_kernel<<<1, 32>>>(made_bf, lu_lower, lu_upper, lu_diag);
    prelude_kernel<<<BATCH / 256, 256>>>(z0, x, sigma, n1_w1, n1_b1, n1_w2, n1_b2,
                                         n2_w1, n2_b1, n2_w2, n2_b2);
    for (int i = 0; i < NLAYER; i++) {
        layer_kernel<<<BATCH / HDIM, 256, DYN_SMEM>>>(
            i, (i == NLAYER - 1) ? 1 : 0,
            made_W0, made_b0, made_bres, made_bf, lu_bias, perms, out);
    }
    (void)in_sizes; (void)n_in; (void)out_size;
}

// round 4
// speedup vs baseline: 41.5362x; 17.2577x over previous
#include <cuda_runtime.h>
#include <cuda_bf16.h>
#include <math.h>
#include <stdint.h>

// ---------------------------------------------------------------------------
// NeuralSplineFlow forward — tabulated-MADE version.
// Key insight: the MADE MLP depends only on the scalar out0 (M0 masks col 1,
// MF masks dim-0 heads), so out0 -> p1[23] is a 1-D piecewise-LINEAR map
// (ReLU net). We tabulate it per layer on a uniform grid (exact lerp between
// kinks) using the R3 split-bf16 mma.sync machinery (1/32 of the per-sample
// GEMM work), then run the whole 16-layer flow in ONE fused kernel with a
// 192-byte lerp instead of 5 GEMMs per sample-layer. Samples whose out0
// falls outside the table range use an exact warp-cooperative MLP fallback.
// ---------------------------------------------------------------------------

#define BATCH   262144
#define NLAYER  16
#define HDIM    128
#define NBINS   8
#define PMVAL   23
#define TBV     3.0f
#define MINWV   0.001f
#define MINDV   0.001f
#define LUEPS   0.001f
#define INV_SQH 0.08838834764831843f   // 1/sqrt(128)

// table
#define TS      8192
#define TLO     (-16.0f)
#define TDELTA  0.00390625f            // 1/256
#define TINVD   256.0f

// SMEM geometry for the table-build (R3 mma) kernel
#define KSTRIDE   136
#define ROWB      (KSTRIDE * 2)
#define ACT_BYTES (HDIM * ROWB)          // 34816
#define WMAT_ELEMS (HDIM * KSTRIDE)
#define WSLOT_BYTES (2 * ACT_BYTES)      // 69632
#define WF_STRIDE 40
#define WF_HALF   (HDIM * WF_STRIDE)
#define WF_BYTES  (2 * WF_HALF * 2)

#define OFF_ACTHI 0
#define OFF_ACTLO 34816
#define OFF_SLOT0 69632
#define OFF_SLOT1 139264
#define OFF_P1    139264
#define DYN_SMEM  208896

// ----------------------------- device scratch ------------------------------
__device__ __align__(16) uint16_t g_Wimg[NLAYER * 4 * 2 * WMAT_ELEMS];
__device__ __align__(16) uint16_t g_Wfimg[NLAYER * 2 * WF_HALF];
__device__ __align__(16) float g_table[NLAYER * TS * 24];   // p1 + bf1, padded
__device__ float g_cw0[NLAYER * 9];
__device__ float g_w0[NLAYER * 8];
__device__ float g_ch0[NLAYER * 9];
__device__ float g_h0[NLAYER * 8];
__device__ float g_d0[NLAYER * 9];
__device__ float g_invW[NLAYER * 4];
__device__ float g_ldinit;

// ----------------------------- PTX helpers ---------------------------------
__device__ __forceinline__ uint32_t smem_u32(const void* p) {
    uint32_t a;
    asm("{ .reg .u64 t; cvta.to.shared.u64 t, %1; cvt.u32.u64 %0, t; }"
        : "=r"(a) : "l"(p));
    return a;
}
__device__ __forceinline__ void ldmA4(uint32_t a[4], uint32_t addr) {
    asm volatile("ldmatrix.sync.aligned.m8n8.x4.shared.b16 {%0,%1,%2,%3}, [%4];"
        : "=r"(a[0]), "=r"(a[1]), "=r"(a[2]), "=r"(a[3]) : "r"(addr));
}
__device__ __forceinline__ void ldmB4t(uint32_t b[4], uint32_t addr) {
    asm volatile("ldmatrix.sync.aligned.m8n8.x4.trans.shared.b16 {%0,%1,%2,%3}, [%4];"
        : "=r"(b[0]), "=r"(b[1]), "=r"(b[2]), "=r"(b[3]) : "r"(addr));
}
__device__ __forceinline__ void mmabf(float d[4], const uint32_t a[4],
                                      uint32_t b0, uint32_t b1) {
    asm volatile("mma.sync.aligned.m16n8k16.row.col.f32.bf16.bf16.f32 "
        "{%0,%1,%2,%3}, {%4,%5,%6,%7}, {%8,%9}, {%0,%1,%2,%3};"
        : "+f"(d[0]), "+f"(d[1]), "+f"(d[2]), "+f"(d[3])
        : "r"(a[0]), "r"(a[1]), "r"(a[2]), "r"(a[3]), "r"(b0), "r"(b1));
}
__device__ __forceinline__ void cpasync16(uint32_t dst, const void* src) {
    asm volatile("cp.async.cg.shared.global [%0], [%1], 16;"
                 :: "r"(dst), "l"(src));
}
#define CP_COMMIT() asm volatile("cp.async.commit_group;" ::: "memory")
#define CP_WAIT0()  asm volatile("cp.async.wait_group 0;" ::: "memory")

// ----------------------------- math helpers --------------------------------
__device__ __forceinline__ float softplusf(float x) {
    return fmaxf(x, 0.f) + log1pf(expf(-fabsf(x)));
}

__device__ void build_params(const float* uw, const float* uh, const float* ud,
                             float* cw, float* w, float* ch, float* hh, float* dd) {
    {
        float mx = uw[0];
        #pragma unroll
        for (int k = 1; k < NBINS; k++) mx = fmaxf(mx, uw[k]);
        float e[NBINS]; float s = 0.f;
        #pragma unroll
        for (int k = 0; k < NBINS; k++) { e[k] = expf(uw[k] - mx); s += e[k]; }
        float inv = 1.f / s;
        cw[0] = -TBV; float cum = 0.f;
        #pragma unroll
        for (int k = 0; k < NBINS; k++) {
            float wk = MINWV + (1.f - MINWV * NBINS) * e[k] * inv;
            cum += wk;
            cw[k + 1] = 2.f * TBV * cum - TBV;
        }
        cw[NBINS] = TBV;
        #pragma unroll
        for (int k = 0; k < NBINS; k++) w[k] = cw[k + 1] - cw[k];
    }
    {
        float mx = uh[0];
        #pragma unroll
        for (int k = 1; k < NBINS; k++) mx = fmaxf(mx, uh[k]);
        float e[NBINS]; float s = 0.f;
        #pragma unroll
        for (int k = 0; k < NBINS; k++) { e[k] = expf(uh[k] - mx); s += e[k]; }
        float inv = 1.f / s;
        ch[0] = -TBV; float cum = 0.f;
        #pragma unroll
        for (int k = 0; k < NBINS; k++) {
            float hk = MINWV + (1.f - MINWV * NBINS) * e[k] * inv;
            cum += hk;
            ch[k + 1] = 2.f * TBV * cum - TBV;
        }
        ch[NBINS] = TBV;
        #pragma unroll
        for (int k = 0; k < NBINS; k++) hh[k] = ch[k + 1] - ch[k];
    }
    dd[0] = 1.0f;
    #pragma unroll
    for (int k = 0; k < 7; k++) dd[k + 1] = MINDV + softplusf(ud[k]);
    dd[NBINS] = 1.0f;
}

__device__ void rqs_inverse(float y, const float* cw, const float* w,
                            const float* ch, const float* hh, const float* dd,
                            float& xout, float& ldout) {
    bool inside = (y >= -TBV) && (y <= TBV);
    float yc = fminf(fmaxf(y, -TBV), TBV);
    int idx = 0;
    #pragma unroll
    for (int k = 1; k <= NBINS; k++) idx += (yc >= ch[k]) ? 1 : 0;
    idx = min(idx, NBINS - 1);
    float yk = ch[idx], hk = hh[idx], xk = cw[idx], wk = w[idx];
    float dk = dd[idx], dk1 = dd[idx + 1];
    float sk = hk / wk;
    float dy = yc - yk;
    float t2 = dk + dk1 - 2.f * sk;
    float qa = dy * t2 + hk * (sk - dk);
    float qb = hk * dk - dy * t2;
    float qc = -sk * dy;
    float disc = fmaxf(qb * qb - 4.f * qa * qc, 0.f);
    float theta = 2.f * qc / (-qb - sqrtf(disc));
    float xo = theta * wk + xk;
    float om = 1.f - theta;
    float denom = sk + t2 * theta * om;
    float dnum = sk * sk * (dk1 * theta * theta + 2.f * sk * theta * om + dk * om * om);
    float ldf = logf(dnum) - 2.f * logf(denom);
    xout  = inside ? xo : y;
    ldout = inside ? -ldf : 0.f;
}

__device__ __forceinline__ void split2(float a, float b, uint32_t& hi, uint32_t& lo) {
    __nv_bfloat16 ah = __float2bfloat16(a), bh = __float2bfloat16(b);
    __nv_bfloat16 al = __float2bfloat16(a - __bfloat162float(ah));
    __nv_bfloat16 bl = __float2bfloat16(b - __bfloat162float(bh));
    hi = (uint32_t)__bfloat16_as_ushort(ah) | ((uint32_t)__bfloat16_as_ushort(bh) << 16);
    lo = (uint32_t)__bfloat16_as_ushort(al) | ((uint32_t)__bfloat16_as_ushort(bl) << 16);
}

// ------------------------------ setup kernels ------------------------------
__global__ void build_wimg_kernel(const float* __restrict__ Wres,
                                  const float* __restrict__ Wf) {
    const int total1 = NLAYER * 4 * HDIM * KSTRIDE;
    for (int t = blockIdx.x * blockDim.x + threadIdx.x; t < total1;
         t += gridDim.x * blockDim.x) {
        int n  = t % KSTRIDE;
        int k  = (t / KSTRIDE) % HDIM;
        int mg = t / (KSTRIDE * HDIM);
        float v = (n < HDIM) ? Wres[mg * 16384 + n * HDIM + k] : 0.f;
        __nv_bfloat16 h = __float2bfloat16(v);
        __nv_bfloat16 l = __float2bfloat16(v - __bfloat162float(h));
        int base = (mg * 2) * WMAT_ELEMS + k * KSTRIDE + n;
        g_Wimg[base]              = __bfloat16_as_ushort(h);
        g_Wimg[base + WMAT_ELEMS] = __bfloat16_as_ushort(l);
    }
    const int total2 = NLAYER * HDIM * WF_STRIDE;
    for (int t = blockIdx.x * blockDim.x + threadIdx.x; t < total2;
         t += gridDim.x * blockDim.x) {
        int n  = t % WF_STRIDE;
        int k  = (t / WF_STRIDE) % HDIM;
        int ly = t / (WF_STRIDE * HDIM);
        float v = (n < PMVAL) ? Wf[(ly * (2 * PMVAL) + PMVAL + n) * HDIM + k] : 0.f;
        __nv_bfloat16 h = __float2bfloat16(v);
        __nv_bfloat16 l = __float2bfloat16(v - __bfloat162float(h));
        int base = (ly * 2) * WF_HALF + k * WF_STRIDE + n;
        g_Wfimg[base]           = __bfloat16_as_ushort(h);
        g_Wfimg[base + WF_HALF] = __bfloat16_as_ushort(l);
    }
}

__global__ void setup_kernel(const float* __restrict__ made_bf,
                             const float* __restrict__ lu_lower,
                             const float* __restrict__ lu_upper,
                             const float* __restrict__ lu_diag) {
    __shared__ float sldl[NLAYER];
    int i = threadIdx.x;
    if (i < NLAYER) {
        const float* bfL = made_bf + i * (2 * PMVAL);
        float uw[8], uh[8], ud[7];
        #pragma unroll
        for (int k = 0; k < 8; k++) { uw[k] = bfL[k] * INV_SQH; uh[k] = bfL[8 + k] * INV_SQH; }
        #pragma unroll
        for (int k = 0; k < 7; k++) ud[k] = bfL[16 + k];
        build_params(uw, uh, ud, g_cw0 + 9 * i, g_w0 + 8 * i,
                     g_ch0 + 9 * i, g_h0 + 8 * i, g_d0 + 9 * i);
        float l = lu_lower[i], u = lu_upper[i];
        float d0 = softplusf(lu_diag[2 * i]) + LUEPS;
        float d1 = softplusf(lu_diag[2 * i + 1]) + LUEPS;
        float invdet = 1.f / (d0 * d1);
        g_invW[4 * i + 0] = (l * u + d1) * invdet;
        g_invW[4 * i + 1] = -u * invdet;
        g_invW[4 * i + 2] = -l * d0 * invdet;
        g_invW[4 * i + 3] = d0 * invdet;
        sldl[i] = logf(d0) + logf(d1);
    }
    __syncthreads();
    if (i == 0) {
        float s = 0.f;
        for (int j = 0; j < NLAYER; j++) s += sldl[j];
        g_ldinit = -s;
    }
}

// ------------------------- table-build (mma) kernel -------------------------
__device__ __forceinline__ void prefetch_w(uint32_t dst_u, const uint16_t* gsrc,
                                           int chunks, int tid) {
    const char* s = (const char*)gsrc;
    for (int i = tid; i < chunks; i += 256)
        cpasync16(dst_u + i * 16, s + i * 16);
    CP_COMMIT();
}

__global__ void __launch_bounds__(256, 1)
table_build_kernel(const float* __restrict__ made_W0,   // (16,128,2)
                   const float* __restrict__ made_b0,   // (16,128)
                   const float* __restrict__ made_bres, // (16,2,2,128)
                   const float* __restrict__ made_bf) { // (16,46)
    extern __shared__ char dynsm[];
    __shared__ float s_bias[4][HDIM];
    __shared__ float s_out0[HDIM];
    __shared__ float s_w0col[HDIM], s_b0[HDIM];

    const int layer = blockIdx.x >> 6;           // 64 tiles per layer
    const int tile  = blockIdx.x & 63;
    const int tid   = threadIdx.x;
    const int lane  = tid & 31;
    const int w     = tid >> 5;

    const uint32_t base_u  = smem_u32(dynsm);
    const uint32_t actHi_u = base_u + OFF_ACTHI;
    const uint32_t slot_u[2] = { base_u + OFF_SLOT0, base_u + OFF_SLOT1 };

    prefetch_w(slot_u[0], g_Wimg + (size_t)(layer * 4) * (2 * WMAT_ELEMS),
               WSLOT_BYTES / 16, tid);

    if (tid < HDIM) {
        s_w0col[tid] = made_W0[(layer * HDIM + tid) * 2];
        s_b0[tid]    = made_b0[layer * HDIM + tid];
        s_out0[tid]  = TLO + (float)(tile * HDIM + tid) * TDELTA;  // grid point
    }
    for (int i = tid; i < 4 * HDIM; i += 256)
        s_bias[i >> 7][i & 127] = made_bres[layer * 4 * HDIM + i];
    __syncthreads();

    const int r0 = w * 16 + (lane >> 2);
    const int r1 = r0 + 8;
    const int cB = (lane & 3) * 2;
    const uint32_t o0 = (uint32_t)r0 * ROWB + cB * 2;
    const uint32_t o1 = (uint32_t)r1 * ROWB + cB * 2;

    float H[64];
    {
        float oa = s_out0[r0], ob = s_out0[r1];
        #pragma unroll
        for (int t = 0; t < 16; t++) {
            int c = t * 8 + cB;
            float2 wc = *(const float2*)&s_w0col[c];
            float2 bc = *(const float2*)&s_b0[c];
            float h0 = fmaf(oa, wc.x, bc.x), h1 = fmaf(oa, wc.y, bc.y);
            float h2 = fmaf(ob, wc.x, bc.x), h3 = fmaf(ob, wc.y, bc.y);
            H[t * 4] = h0; H[t * 4 + 1] = h1; H[t * 4 + 2] = h2; H[t * 4 + 3] = h3;
            uint32_t hi0, lo0, hi1, lo1;
            split2(fmaxf(h0, 0.f), fmaxf(h1, 0.f), hi0, lo0);
            split2(fmaxf(h2, 0.f), fmaxf(h3, 0.f), hi1, lo1);
            *(uint32_t*)(dynsm + OFF_ACTHI + o0 + t * 16) = hi0;
            *(uint32_t*)(dynsm + OFF_ACTHI + o1 + t * 16) = hi1;
            *(uint32_t*)(dynsm + OFF_ACTLO + o0 + t * 16) = lo0;
            *(uint32_t*)(dynsm + OFF_ACTLO + o1 + t * 16) = lo1;
        }
    }
    CP_WAIT0();
    __syncthreads();

    const uint32_t aHiBase = actHi_u + (uint32_t)(w * 16 + (lane & 15)) * ROWB
                             + ((lane >> 4) * 16);
    const uint32_t aLoBase = aHiBase + ACT_BYTES;
    const uint32_t bOff    = (uint32_t)(lane & 15) * ROWB + ((lane >> 4) * 16);
    const uint32_t wfOff   = (uint32_t)(lane & 15) * (WF_STRIDE * 2) + ((lane >> 4) * 16);

    #pragma unroll 1
    for (int g = 0; g < 4; g++) {
        if (g < 3)
            prefetch_w(slot_u[(g + 1) & 1],
                       g_Wimg + (size_t)(layer * 4 + g + 1) * (2 * WMAT_ELEMS),
                       WSLOT_BYTES / 16, tid);
        else
            prefetch_w(slot_u[0], g_Wfimg + (size_t)layer * (2 * WF_HALF),
                       WF_BYTES / 16, tid);

        __syncwarp();
        uint32_t Ah[8][4], Al[8][4];
        #pragma unroll
        for (int kc = 0; kc < 8; kc++) {
            ldmA4(Ah[kc], aHiBase + kc * 32);
            ldmA4(Al[kc], aLoBase + kc * 32);
        }
        const uint32_t wbase = slot_u[g & 1] + bOff;

        #pragma unroll
        for (int tp = 0; tp < 8; tp++) {
            float D0[4] = {0.f, 0.f, 0.f, 0.f};
            float D1[4] = {0.f, 0.f, 0.f, 0.f};
            #pragma unroll
            for (int kc = 0; kc < 8; kc++) {
                uint32_t bh[4], bl[4];
                ldmB4t(bh, wbase + kc * (16 * ROWB) + tp * 32);
                ldmB4t(bl, wbase + ACT_BYTES + kc * (16 * ROWB) + tp * 32);
                mmabf(D0, Ah[kc], bh[0], bh[1]);
                mmabf(D0, Al[kc], bh[0], bh[1]);
                mmabf(D0, Ah[kc], bl[0], bl[1]);
                mmabf(D1, Ah[kc], bh[2], bh[3]);
                mmabf(D1, Al[kc], bh[2], bh[3]);
                mmabf(D1, Ah[kc], bl[2], bl[3]);
            }
            #pragma unroll
            for (int q = 0; q < 2; q++) {
                const int t = tp * 2 + q;
                float* D = q ? D1 : D0;
                float2 bb = *(const float2*)&s_bias[g][t * 8 + cB];
                float v0, v1, v2, v3;
                if ((g & 1) == 0) {
                    v0 = fmaxf(D[0] + bb.x, 0.f);
                    v1 = fmaxf(D[1] + bb.y, 0.f);
                    v2 = fmaxf(D[2] + bb.x, 0.f);
                    v3 = fmaxf(D[3] + bb.y, 0.f);
                } else {
                    float n0 = H[t * 4]     + D[0] + bb.x;
                    float n1 = H[t * 4 + 1] + D[1] + bb.y;
                    float n2 = H[t * 4 + 2] + D[2] + bb.x;
                    float n3 = H[t * 4 + 3] + D[3] + bb.y;
                    H[t * 4] = n0; H[t * 4 + 1] = n1;
                    H[t * 4 + 2] = n2; H[t * 4 + 3] = n3;
                    if (g == 3) { v0 = n0; v1 = n1; v2 = n2; v3 = n3; }
                    else { v0 = fmaxf(n0, 0.f); v1 = fmaxf(n1, 0.f);
                           v2 = fmaxf(n2, 0.f); v3 = fmaxf(n3, 0.f); }
                }
                uint32_t hi0, lo0, hi1, lo1;
                split2(v0, v1, hi0, lo0);
                split2(v2, v3, hi1, lo1);
                *(uint32_t*)(dynsm + OFF_ACTHI + o0 + t * 16) = hi0;
                *(uint32_t*)(dynsm + OFF_ACTHI + o1 + t * 16) = hi1;
                *(uint32_t*)(dynsm + OFF_ACTLO + o0 + t * 16) = lo0;
                *(uint32_t*)(dynsm + OFF_ACTLO + o1 + t * 16) = lo1;
            }
        }
        CP_WAIT0();
        __syncthreads();
    }

    // Wf GEMM: p1 = h @ Wf^T
    {
        __syncwarp();
        uint32_t Ah[8][4], Al[8][4];
        #pragma unroll
        for (int kc = 0; kc < 8; kc++) {
            ldmA4(Ah[kc], aHiBase + kc * 32);
            ldmA4(Al[kc], aLoBase + kc * 32);
        }
        const uint32_t wfb = slot_u[0] + wfOff;
        float* p1 = (float*)(dynsm + OFF_P1);
        #pragma unroll
        for (int tp = 0; tp < 2; tp++) {
            float D0[4] = {0.f, 0.f, 0.f, 0.f};
            float D1[4] = {0.f, 0.f, 0.f, 0.f};
            #pragma unroll
            for (int kc = 0; kc < 8; kc++) {
                uint32_t bh[4], bl[4];
                ldmB4t(bh, wfb + kc * (16 * WF_STRIDE * 2) + tp * 32);
                ldmB4t(bl, wfb + 2 * WF_HALF + kc * (16 * WF_STRIDE * 2) + tp * 32);
                mmabf(D0, Ah[kc], bh[0], bh[1]);
                mmabf(D0, Al[kc], bh[0], bh[1]);
                mmabf(D0, Ah[kc], bl[0], bl[1]);
                mmabf(D1, Ah[kc], bh[2], bh[3]);
                mmabf(D1, Al[kc], bh[2], bh[3]);
                mmabf(D1, Ah[kc], bl[2], bl[3]);
            }
            int c0 = tp * 16 + cB;
            p1[r0 * 26 + c0] = D0[0]; p1[r0 * 26 + c0 + 1] = D0[1];
            p1[r1 * 26 + c0] = D0[2]; p1[r1 * 26 + c0 + 1] = D0[3];
            if (tp == 0) {
                p1[r0 * 26 + c0 + 8] = D1[0]; p1[r0 * 26 + c0 + 9] = D1[1];
                p1[r1 * 26 + c0 + 8] = D1[2]; p1[r1 * 26 + c0 + 9] = D1[3];
            }
        }
    }
    __syncthreads();

    // write table row: p1 + bf1
    if (tid < HDIM) {
        const float* p1r = (const float*)(dynsm + OFF_P1) + tid * 26;
        const float* bf1 = made_bf + layer * (2 * PMVAL) + PMVAL;
        float* trow = g_table + ((size_t)layer * TS + tile * HDIM + tid) * 24;
        #pragma unroll
        for (int m = 0; m < PMVAL; m++) trow[m] = p1r[m] + bf1[m];
        trow[23] = 0.f;
    }
}

// ------------------------- exact MLP fallback (rare) ------------------------
// Whole warp cooperatively evaluates the MADE net at one scalar; h distributed
// 4 values/lane (strided: value j lives in reg j>>5 of lane j&31).
__device__ void made_fallback(unsigned need, float out0_self, int l,
                              const float* __restrict__ W0,
                              const float* __restrict__ b0,
                              const float* __restrict__ Wres,
                              const float* __restrict__ bres,
                              const float* __restrict__ Wf,
                              const float* __restrict__ bf,
                              float* p1out, int lane) {
    while (need) {
        int src = __ffs(need) - 1;
        need &= need - 1;
        float x0 = __shfl_sync(0xffffffffu, out0_self, src);
        float h[4];
        #pragma unroll
        for (int jj = 0; jj < 4; jj++) {
            int j = jj * 32 + lane;
            h[jj] = fmaf(x0, W0[(l * HDIM + j) * 2], b0[l * HDIM + j]);
        }
        #pragma unroll 1
        for (int blk = 0; blk < 2; blk++) {
            float v[4], a1[4], a2[4];
            #pragma unroll
            for (int jj = 0; jj < 4; jj++) v[jj] = fmaxf(h[jj], 0.f);
            const float* Wa = Wres + (size_t)((l * 2 + blk) * 2 + 0) * 16384;
            const float* ba = bres + ((l * 2 + blk) * 2 + 0) * 128;
            #pragma unroll
            for (int jj = 0; jj < 4; jj++) a1[jj] = ba[jj * 32 + lane];
            for (int kk = 0; kk < 4; kk++) {
                float vv = v[kk];
                for (int k2 = 0; k2 < 32; k2++) {
                    float vk = __shfl_sync(0xffffffffu, vv, k2);
                    int k = kk * 32 + k2;
                    #pragma unroll
                    for (int jj = 0; jj < 4; jj++)
                        a1[jj] = fmaf(Wa[(jj * 32 + lane) * 128 + k], vk, a1[jj]);
                }
            }
            #pragma unroll
            for (int jj = 0; jj < 4; jj++) a1[jj] = fmaxf(a1[jj], 0.f);
            const float* Wb = Wres + (size_t)((l * 2 + blk) * 2 + 1) * 16384;
            const float* bb = bres + ((l * 2 + blk) * 2 + 1) * 128;
            #pragma unroll
            for (int jj = 0; jj < 4; jj++) a2[jj] = bb[jj * 32 + lane];
            for (int kk = 0; kk < 4; kk++) {
                float vv = a1[kk];
                for (int k2 = 0; k2 < 32; k2++) {
                    float vk = __shfl_sync(0xffffffffu, vv, k2);
                    int k = kk * 32 + k2;
                    #pragma unroll
                    for (int jj = 0; jj < 4; jj++)
                        a2[jj] = fmaf(Wb[(jj * 32 + lane) * 128 + k], vk, a2[jj]);
                }
            }
            #pragma unroll
            for (int jj = 0; jj < 4; jj++) h[jj] += a2[jj];
        }
        // Wf: p[m] for m = lane < 23 (input = raw h, no relu)
        float accp = (lane < PMVAL) ? bf[l * (2 * PMVAL) + PMVAL + lane] : 0.f;
        for (int kk = 0; kk < 4; kk++) {
            float hv = h[kk];
            for (int k2 = 0; k2 < 32; k2++) {
                float vk = __shfl_sync(0xffffffffu, hv, k2);
                int k = kk * 32 + k2;
                if (lane < PMVAL)
                    accp = fmaf(Wf[((size_t)l * (2 * PMVAL) + PMVAL + lane) * 128 + k],
                                vk, accp);
            }
        }
        #pragma unroll
        for (int m = 0; m < PMVAL; m++) {
            float pm = __shfl_sync(0xffffffffu, accp, m);
            if (lane == src) p1out[m] = pm;
        }
    }
}

// ------------------------------ fused flow kernel ---------------------------
__global__ void __launch_bounds__(256)
flow_kernel(const float* __restrict__ z0in, const float* __restrict__ xin,
            const float* __restrict__ sigma,
            const float* __restrict__ n1w1, const float* __restrict__ n1b1,
            const float* __restrict__ n1w2, const float* __restrict__ n1b2,
            const float* __restrict__ n2w1, const float* __restrict__ n2b1,
            const float* __restrict__ n2w2, const float* __restrict__ n2b2,
            const float* __restrict__ made_W0, const float* __restrict__ made_b0,
            const float* __restrict__ made_Wres, const float* __restrict__ made_bres,
            const float* __restrict__ made_Wf, const float* __restrict__ made_bf,
            const float* __restrict__ lu_bias, const int* __restrict__ perms,
            float* __restrict__ out) {
    __shared__ float s1w[32], s1b[32], s1o[64], s1ob[2];
    __shared__ float s2w[128], s2b[32], s2o[64], s2ob[2];
    __shared__ float sld;
    __shared__ float sc_cw[NLAYER][9], sc_w[NLAYER][8], sc_ch[NLAYER][9];
    __shared__ float sc_h[NLAYER][8], sc_d[NLAYER][9];
    __shared__ float sc_invW[NLAYER][4], sc_b2[NLAYER][2];
    __shared__ int   sc_perm[NLAYER][2];

    const int tid  = threadIdx.x;
    const int lane = tid & 31;

    if (tid < 32) { s1w[tid] = n1w1[tid]; s1b[tid] = n1b1[tid]; s2b[tid] = n2b1[tid]; }
    if (tid < 64) { s1o[tid] = n1w2[tid]; s2o[tid] = n2w2[tid]; }
    if (tid < 128) s2w[tid] = n2w1[tid];
    if (tid < 2)  { s1ob[tid] = n1b2[tid]; s2ob[tid] = n2b2[tid]; }
    if (tid == 0) sld = g_ldinit;
    for (int i = tid; i < NLAYER * 9; i += 256) {
        sc_cw[i / 9][i % 9] = g_cw0[i];
        sc_ch[i / 9][i % 9] = g_ch0[i];
        sc_d [i / 9][i % 9] = g_d0[i];
    }
    for (int i = tid; i < NLAYER * 8; i += 256) {
        sc_w[i / 8][i % 8] = g_w0[i];
        sc_h[i / 8][i % 8] = g_h0[i];
    }
    for (int i = tid; i < NLAYER * 4; i += 256) sc_invW[i / 4][i % 4] = g_invW[i];
    for (int i = tid; i < NLAYER * 2; i += 256) {
        sc_b2[i / 2][i % 2]   = lu_bias[i];
        sc_perm[i / 2][i % 2] = perms[i];
    }
    __syncthreads();

    const int row = blockIdx.x * 256 + tid;

    // ---- prelude (fused) ----
    float sg = sigma[row];
    float a0 = z0in[2 * row], a1 = z0in[2 * row + 1];
    float b0v = xin[2 * row], b1v = xin[2 * row + 1];
    float t0 = s1ob[0], t1 = s1ob[1];
    #pragma unroll
    for (int j = 0; j < 32; j++) {
        float hv = s1w[j] * sg + s1b[j];
        hv = hv / (1.f + expf(-hv));
        t0 += s1o[j] * hv;
        t1 += s1o[32 + j] * hv;
    }
    float zc0 = s2ob[0], zc1 = s2ob[1];
    #pragma unroll
    for (int j = 0; j < 32; j++) {
        float hv = s2w[4 * j] * a0 + s2w[4 * j + 1] * a1
                 + s2w[4 * j + 2] * b0v + s2w[4 * j + 3] * b1v + s2b[j];
        hv = hv / (1.f + expf(-hv));
        zc0 += s2o[j] * hv;
        zc1 += s2o[32 + j] * hv;
    }
    float z0 = zc0 + t0;
    float z1 = zc1 + t1;
    float ld = sld;

    // ---- 16 layers ----
    #pragma unroll 1
    for (int l = 0; l < NLAYER; l++) {
        float out0, ldp0;
        rqs_inverse(z0, sc_cw[l], sc_w[l], sc_ch[l], sc_h[l], sc_d[l], out0, ldp0);

        float p1[24];
        float u = (out0 - TLO) * TINVD;
        bool inr = (u >= 0.f) && (u <= (float)(TS - 2) + 0.999f);
        if (inr) {
            int i = (int)u;
            float f = u - (float)i;
            const float4* ra = (const float4*)(g_table + ((size_t)l * TS + i) * 24);
            const float4* rb = (const float4*)(g_table + ((size_t)l * TS + i + 1) * 24);
            #pragma unroll
            for (int q = 0; q < 6; q++) {
                float4 va = ra[q], vb = rb[q];
                p1[4 * q]     = va.x + f * (vb.x - va.x);
                p1[4 * q + 1] = va.y + f * (vb.y - va.y);
                p1[4 * q + 2] = va.z + f * (vb.z - va.z);
                p1[4 * q + 3] = va.w + f * (vb.w - va.w);
            }
        }
        unsigned need = __ballot_sync(0xffffffffu, !inr);
        if (need)
            made_fallback(need, out0, l, made_W0, made_b0, made_Wres, made_bres,
                          made_Wf, made_bf, p1, lane);

        float uw[8], uh[8], ud[7];
        #pragma unroll
        for (int k = 0; k < 8; k++) { uw[k] = p1[k] * INV_SQH; uh[k] = p1[8 + k] * INV_SQH; }
        #pragma unroll
        for (int k = 0; k < 7; k++) ud[k] = p1[16 + k];
        float cw[9], ww[8], chh[9], hh2[8], dd[9];
        build_params(uw, uh, ud, cw, ww, chh, hh2, dd);
        float out1, ldp1;
        rqs_inverse(z1, cw, ww, chh, hh2, dd, out1, ldp1);

        ld += ldp0 + ldp1;
        float v0 = out0 - sc_b2[l][0];
        float v1 = out1 - sc_b2[l][1];
        float zz0 = sc_invW[l][0] * v0 + sc_invW[l][1] * v1;
        float zz1 = sc_invW[l][2] * v0 + sc_invW[l][3] * v1;
        z0 = sc_perm[l][0] ? zz1 : zz0;
        z1 = sc_perm[l][1] ? zz1 : zz0;
    }

    out[2 * row]         = z0;
    out[2 * row + 1]     = z1;
    out[2 * BATCH + row] = ld;
}

// ------------------------------ launcher -----------------------------------
extern "C" void kernel_launch(void* const* d_in, const int* in_sizes, int n_in,
                              void* d_out, int out_size) {
    const float* z0      = (const float*)d_in[0];
    const float* x       = (const float*)d_in[1];
    const float* sigma   = (const float*)d_in[2];
    const float* n1_w1   = (const float*)d_in[3];
    const float* n1_b1   = (const float*)d_in[4];
    const float* n1_w2   = (const float*)d_in[5];
    const float* n1_b2   = (const float*)d_in[6];
    const float* n2_w1   = (const float*)d_in[7];
    const float* n2_b1   = (const float*)d_in[8];
    const float* n2_w2   = (const float*)d_in[9];
    const float* n2_b2   = (const float*)d_in[10];
    const float* made_W0 = (const float*)d_in[11];
    const float* made_b0 = (const float*)d_in[12];
    const float* made_Wres = (const float*)d_in[13];
    const float* made_bres = (const float*)d_in[14];
    const float* made_Wf   = (const float*)d_in[15];
    const float* made_bf   = (const float*)d_in[16];
    const float* lu_lower  = (const float*)d_in[17];
    const float* lu_upper  = (const float*)d_in[18];
    const float* lu_diag   = (const float*)d_in[19];
    const float* lu_bias   = (const float*)d_in[20];
    const int*   perms     = (const int*)d_in[21];
    float* out = (float*)d_out;

    cudaFuncSetAttribute(table_build_kernel,
                         cudaFuncAttributeMaxDynamicSharedMemorySize, DYN_SMEM);

    build_wimg_kernel<<<2048, 256>>>(made_Wres, made_Wf);
    setup_kernel<<<1, 32>>>(made_bf, lu_lower, lu_upper, lu_diag);
    table_build_kernel<<<NLAYER * (TS / HDIM), 256, DYN_SMEM>>>(
        made_W0, made_b0, made_bres, made_bf);
    flow_kernel<<<BATCH / 256, 256>>>(
        z0, x, sigma, n1_w1, n1_b1, n1_w2, n1_b2,
        n2_w1, n2_b1, n2_w2, n2_b2,
        made_W0, made_b0, made_Wres, made_bres, made_Wf, made_bf,
        lu_bias, perms, out);
    (void)in_sizes; (void)n_in; (void)out_size;
}

// round 5
// speedup vs baseline: 60.0925x; 1.4467x over previous
#include <cuda_runtime.h>
#include <cuda_bf16.h>
#include <math.h>
#include <stdint.h>

// ---------------------------------------------------------------------------
// NeuralSplineFlow forward — tabulated-MADE, register-resident splines.
// R4 insight: MADE net is a 1-D PWL map out0 -> p1[23]; tabulated per layer
// (split-bf16 mma.sync build), flow is one fused kernel with a lerp.
// R5: predicated-select spline (no local memory), fast intrinsics, table
// delta 1/256 -> 1/128 (same [-16,16] range, half the build cost).
// ---------------------------------------------------------------------------

#define BATCH   262144
#define NLAYER  16
#define HDIM    128
#define NBINS   8
#define PMVAL   23
#define TBV     3.0f
#define MINWV   0.001f
#define MINDV   0.001f
#define LUEPS   0.001f
#define INV_SQH 0.08838834764831843f   // 1/sqrt(128)

// table
#define TS      4096
#define TLO     (-16.0f)
#define TDELTA  0.0078125f             // 1/128
#define TINVD   128.0f

// SMEM geometry for the table-build (mma) kernel
#define KSTRIDE   136
#define ROWB      (KSTRIDE * 2)
#define ACT_BYTES (HDIM * ROWB)          // 34816
#define WMAT_ELEMS (HDIM * KSTRIDE)
#define WSLOT_BYTES (2 * ACT_BYTES)      // 69632
#define WF_STRIDE 40
#define WF_HALF   (HDIM * WF_STRIDE)
#define WF_BYTES  (2 * WF_HALF * 2)

#define OFF_ACTHI 0
#define OFF_ACTLO 34816
#define OFF_SLOT0 69632
#define OFF_SLOT1 139264
#define OFF_P1    139264
#define DYN_SMEM  208896

// ----------------------------- device scratch ------------------------------
__device__ __align__(16) uint16_t g_Wimg[NLAYER * 4 * 2 * WMAT_ELEMS];
__device__ __align__(16) uint16_t g_Wfimg[NLAYER * 2 * WF_HALF];
__device__ __align__(16) float g_table[NLAYER * TS * 24];   // p1 + bf1, padded
__device__ float g_cw0[NLAYER * 9];
__device__ float g_w0[NLAYER * 8];
__device__ float g_ch0[NLAYER * 9];
__device__ float g_h0[NLAYER * 8];
__device__ float g_d0[NLAYER * 9];
__device__ float g_invW[NLAYER * 4];
__device__ float g_ldinit;

// ----------------------------- PTX helpers ---------------------------------
__device__ __forceinline__ uint32_t smem_u32(const void* p) {
    uint32_t a;
    asm("{ .reg .u64 t; cvta.to.shared.u64 t, %1; cvt.u32.u64 %0, t; }"
        : "=r"(a) : "l"(p));
    return a;
}
__device__ __forceinline__ void ldmA4(uint32_t a[4], uint32_t addr) {
    asm volatile("ldmatrix.sync.aligned.m8n8.x4.shared.b16 {%0,%1,%2,%3}, [%4];"
        : "=r"(a[0]), "=r"(a[1]), "=r"(a[2]), "=r"(a[3]) : "r"(addr));
}
__device__ __forceinline__ void ldmB4t(uint32_t b[4], uint32_t addr) {
    asm volatile("ldmatrix.sync.aligned.m8n8.x4.trans.shared.b16 {%0,%1,%2,%3}, [%4];"
        : "=r"(b[0]), "=r"(b[1]), "=r"(b[2]), "=r"(b[3]) : "r"(addr));
}
__device__ __forceinline__ void mmabf(float d[4], const uint32_t a[4],
                                      uint32_t b0, uint32_t b1) {
    asm volatile("mma.sync.aligned.m16n8k16.row.col.f32.bf16.bf16.f32 "
        "{%0,%1,%2,%3}, {%4,%5,%6,%7}, {%8,%9}, {%0,%1,%2,%3};"
        : "+f"(d[0]), "+f"(d[1]), "+f"(d[2]), "+f"(d[3])
        : "r"(a[0]), "r"(a[1]), "r"(a[2]), "r"(a[3]), "r"(b0), "r"(b1));
}
__device__ __forceinline__ void cpasync16(uint32_t dst, const void* src) {
    asm volatile("cp.async.cg.shared.global [%0], [%1], 16;"
                 :: "r"(dst), "l"(src));
}
#define CP_COMMIT() asm volatile("cp.async.commit_group;" ::: "memory")
#define CP_WAIT0()  asm volatile("cp.async.wait_group 0;" ::: "memory")

// ----------------------------- math helpers --------------------------------
__device__ __forceinline__ float softplusf(float x) {          // precise (setup)
    return fmaxf(x, 0.f) + log1pf(expf(-fabsf(x)));
}
__device__ __forceinline__ float softplus_fast(float x) {      // flow path
    return fmaxf(x, 0.f) + __logf(1.f + __expf(-fabsf(x)));
}

// precise build (setup kernel only)
__device__ void build_params(const float* uw, const float* uh, const float* ud,
                             float* cw, float* w, float* ch, float* hh, float* dd) {
    {
        float mx = uw[0];
        #pragma unroll
        for (int k = 1; k < NBINS; k++) mx = fmaxf(mx, uw[k]);
        float e[NBINS]; float s = 0.f;
        #pragma unroll
        for (int k = 0; k < NBINS; k++) { e[k] = expf(uw[k] - mx); s += e[k]; }
        float inv = 1.f / s;
        cw[0] = -TBV; float cum = 0.f;
        #pragma unroll
        for (int k = 0; k < NBINS; k++) {
            float wk = MINWV + (1.f - MINWV * NBINS) * e[k] * inv;
            cum += wk;
            cw[k + 1] = 2.f * TBV * cum - TBV;
        }
        cw[NBINS] = TBV;
        #pragma unroll
        for (int k = 0; k < NBINS; k++) w[k] = cw[k + 1] - cw[k];
    }
    {
        float mx = uh[0];
        #pragma unroll
        for (int k = 1; k < NBINS; k++) mx = fmaxf(mx, uh[k]);
        float e[NBINS]; float s = 0.f;
        #pragma unroll
        for (int k = 0; k < NBINS; k++) { e[k] = expf(uh[k] - mx); s += e[k]; }
        float inv = 1.f / s;
        ch[0] = -TBV; float cum = 0.f;
        #pragma unroll
        for (int k = 0; k < NBINS; k++) {
            float hk = MINWV + (1.f - MINWV * NBINS) * e[k] * inv;
            cum += hk;
            ch[k + 1] = 2.f * TBV * cum - TBV;
        }
        ch[NBINS] = TBV;
        #pragma unroll
        for (int k = 0; k < NBINS; k++) hh[k] = ch[k + 1] - ch[k];
    }
    dd[0] = 1.0f;
    #pragma unroll
    for (int k = 0; k < 7; k++) dd[k + 1] = MINDV + softplusf(ud[k]);
    dd[NBINS] = 1.0f;
}

// Register-resident RQS inverse: predicated-select bin search, no dynamic idx.
__device__ __forceinline__ void rqs_reg(float y, const float cw[9], const float w[8],
                                        const float ch[9], const float hh[8],
                                        const float dd[9], float& xout, float& ldout) {
    bool inside = (y >= -TBV) && (y <= TBV);
    float yc = fminf(fmaxf(y, -TBV), TBV);
    float yk = ch[0], hk = hh[0], xk = cw[0], wk = w[0], dk = dd[0], dk1 = dd[1];
    #pragma unroll
    for (int k = 1; k < NBINS; k++) {
        bool c = yc >= ch[k];
        yk  = c ? ch[k]     : yk;
        hk  = c ? hh[k]     : hk;
        xk  = c ? cw[k]     : xk;
        wk  = c ? w[k]      : wk;
        dk  = c ? dd[k]     : dk;
        dk1 = c ? dd[k + 1] : dk1;
    }
    float sk = __fdividef(hk, wk);
    float dy = yc - yk;
    float t2 = dk + dk1 - 2.f * sk;
    float qa = dy * t2 + hk * (sk - dk);
    float qb = hk * dk - dy * t2;
    float qc = -sk * dy;
    float disc = fmaxf(qb * qb - 4.f * qa * qc, 0.f);
    float theta = __fdividef(2.f * qc, -qb - sqrtf(disc));
    float xo = theta * wk + xk;
    float om = 1.f - theta;
    float denom = sk + t2 * theta * om;
    float dnum = sk * sk * (dk1 * theta * theta + 2.f * sk * theta * om + dk * om * om);
    float ldf = __logf(__fdividef(dnum, denom * denom));
    xout  = inside ? xo : y;
    ldout = inside ? -ldf : 0.f;
}

// Fused dim-1 spline: build tables (fast intrinsics) + predicated select.
__device__ __forceinline__ void spline1(float y, const float* p1,
                                        float& xout, float& ldout) {
    float cw[9], ch[9], dd[9];
    {
        float uw[8], uh[8];
        #pragma unroll
        for (int k = 0; k < 8; k++) { uw[k] = p1[k] * INV_SQH; uh[k] = p1[8 + k] * INV_SQH; }
        float mw = uw[0], mh = uh[0];
        #pragma unroll
        for (int k = 1; k < 8; k++) { mw = fmaxf(mw, uw[k]); mh = fmaxf(mh, uh[k]); }
        float ew[8], eh[8], sw = 0.f, sh = 0.f;
        #pragma unroll
        for (int k = 0; k < 8; k++) {
            ew[k] = __expf(uw[k] - mw); sw += ew[k];
            eh[k] = __expf(uh[k] - mh); sh += eh[k];
        }
        float iw = __fdividef(1.f - MINWV * NBINS, sw);
        float ih = __fdividef(1.f - MINWV * NBINS, sh);
        cw[0] = -TBV; ch[0] = -TBV;
        float cumw = 0.f, cumh = 0.f;
        #pragma unroll
        for (int k = 0; k < 7; k++) {
            cumw += MINWV + iw * ew[k];
            cumh += MINWV + ih * eh[k];
            cw[k + 1] = fmaf(2.f * TBV, cumw, -TBV);
            ch[k + 1] = fmaf(2.f * TBV, cumh, -TBV);
        }
        cw[8] = TBV; ch[8] = TBV;
    }
    dd[0] = 1.f; dd[8] = 1.f;
    #pragma unroll
    for (int k = 0; k < 7; k++) dd[k + 1] = MINDV + softplus_fast(p1[16 + k]);

    bool inside = (y >= -TBV) && (y <= TBV);
    float yc = fminf(fmaxf(y, -TBV), TBV);
    float yk = ch[0], yk1 = ch[1], xk = cw[0], xk1 = cw[1], dk = dd[0], dk1 = dd[1];
    #pragma unroll
    for (int k = 1; k < NBINS; k++) {
        bool c = yc >= ch[k];
        yk  = c ? ch[k]     : yk;
        yk1 = c ? ch[k + 1] : yk1;
        xk  = c ? cw[k]     : xk;
        xk1 = c ? cw[k + 1] : xk1;
        dk  = c ? dd[k]     : dk;
        dk1 = c ? dd[k + 1] : dk1;
    }
    float hk = yk1 - yk, wk = xk1 - xk;
    float sk = __fdividef(hk, wk);
    float dy = yc - yk;
    float t2 = dk + dk1 - 2.f * sk;
    float qa = dy * t2 + hk * (sk - dk);
    float qb = hk * dk - dy * t2;
    float qc = -sk * dy;
    float disc = fmaxf(qb * qb - 4.f * qa * qc, 0.f);
    float theta = __fdividef(2.f * qc, -qb - sqrtf(disc));
    float xo = theta * wk + xk;
    float om = 1.f - theta;
    float denom = sk + t2 * theta * om;
    float dnum = sk * sk * (dk1 * theta * theta + 2.f * sk * theta * om + dk * om * om);
    float ldf = __logf(__fdividef(dnum, denom * denom));
    xout  = inside ? xo : y;
    ldout = inside ? -ldf : 0.f;
}

__device__ __forceinline__ void split2(float a, float b, uint32_t& hi, uint32_t& lo) {
    __nv_bfloat16 ah = __float2bfloat16(a), bh = __float2bfloat16(b);
    __nv_bfloat16 al = __float2bfloat16(a - __bfloat162float(ah));
    __nv_bfloat16 bl = __float2bfloat16(b - __bfloat162float(bh));
    hi = (uint32_t)__bfloat16_as_ushort(ah) | ((uint32_t)__bfloat16_as_ushort(bh) << 16);
    lo = (uint32_t)__bfloat16_as_ushort(al) | ((uint32_t)__bfloat16_as_ushort(bl) << 16);
}

// ------------------------------ setup kernels ------------------------------
__global__ void build_wimg_kernel(const float* __restrict__ Wres,
                                  const float* __restrict__ Wf) {
    const int total1 = NLAYER * 4 * HDIM * KSTRIDE;
    for (int t = blockIdx.x * blockDim.x + threadIdx.x; t < total1;
         t += gridDim.x * blockDim.x) {
        int n  = t % KSTRIDE;
        int k  = (t / KSTRIDE) % HDIM;
        int mg = t / (KSTRIDE * HDIM);
        float v = (n < HDIM) ? Wres[mg * 16384 + n * HDIM + k] : 0.f;
        __nv_bfloat16 h = __float2bfloat16(v);
        __nv_bfloat16 l = __float2bfloat16(v - __bfloat162float(h));
        int base = (mg * 2) * WMAT_ELEMS + k * KSTRIDE + n;
        g_Wimg[base]              = __bfloat16_as_ushort(h);
        g_Wimg[base + WMAT_ELEMS] = __bfloat16_as_ushort(l);
    }
    const int total2 = NLAYER * HDIM * WF_STRIDE;
    for (int t = blockIdx.x * blockDim.x + threadIdx.x; t < total2;
         t += gridDim.x * blockDim.x) {
        int n  = t % WF_STRIDE;
        int k  = (t / WF_STRIDE) % HDIM;
        int ly = t / (WF_STRIDE * HDIM);
        float v = (n < PMVAL) ? Wf[(ly * (2 * PMVAL) + PMVAL + n) * HDIM + k] : 0.f;
        __nv_bfloat16 h = __float2bfloat16(v);
        __nv_bfloat16 l = __float2bfloat16(v - __bfloat162float(h));
        int base = (ly * 2) * WF_HALF + k * WF_STRIDE + n;
        g_Wfimg[base]           = __bfloat16_as_ushort(h);
        g_Wfimg[base + WF_HALF] = __bfloat16_as_ushort(l);
    }
}

__global__ void setup_kernel(const float* __restrict__ made_bf,
                             const float* __restrict__ lu_lower,
                             const float* __restrict__ lu_upper,
                             const float* __restrict__ lu_diag) {
    __shared__ float sldl[NLAYER];
    int i = threadIdx.x;
    if (i < NLAYER) {
        const float* bfL = made_bf + i * (2 * PMVAL);
        float uw[8], uh[8], ud[7];
        #pragma unroll
        for (int k = 0; k < 8; k++) { uw[k] = bfL[k] * INV_SQH; uh[k] = bfL[8 + k] * INV_SQH; }
        #pragma unroll
        for (int k = 0; k < 7; k++) ud[k] = bfL[16 + k];
        build_params(uw, uh, ud, g_cw0 + 9 * i, g_w0 + 8 * i,
                     g_ch0 + 9 * i, g_h0 + 8 * i, g_d0 + 9 * i);
        float l = lu_lower[i], u = lu_upper[i];
        float d0 = softplusf(lu_diag[2 * i]) + LUEPS;
        float d1 = softplusf(lu_diag[2 * i + 1]) + LUEPS;
        float invdet = 1.f / (d0 * d1);
        g_invW[4 * i + 0] = (l * u + d1) * invdet;
        g_invW[4 * i + 1] = -u * invdet;
        g_invW[4 * i + 2] = -l * d0 * invdet;
        g_invW[4 * i + 3] = d0 * invdet;
        sldl[i] = logf(d0) + logf(d1);
    }
    __syncthreads();
    if (i == 0) {
        float s = 0.f;
        for (int j = 0; j < NLAYER; j++) s += sldl[j];
        g_ldinit = -s;
    }
}

// ------------------------- table-build (mma) kernel -------------------------
__device__ __forceinline__ void prefetch_w(uint32_t dst_u, const uint16_t* gsrc,
                                           int chunks, int tid) {
    const char* s = (const char*)gsrc;
    for (int i = tid; i < chunks; i += 256)
        cpasync16(dst_u + i * 16, s + i * 16);
    CP_COMMIT();
}

__global__ void __launch_bounds__(256, 1)
table_build_kernel(const float* __restrict__ made_W0,   // (16,128,2)
                   const float* __restrict__ made_b0,   // (16,128)
                   const float* __restrict__ made_bres, // (16,2,2,128)
                   const float* __restrict__ made_bf) { // (16,46)
    extern __shared__ char dynsm[];
    __shared__ float s_bias[4][HDIM];
    __shared__ float s_out0[HDIM];
    __shared__ float s_w0col[HDIM], s_b0[HDIM];

    const int layer = blockIdx.x >> 5;           // 32 tiles per layer (TS=4096)
    const int tile  = blockIdx.x & 31;
    const int tid   = threadIdx.x;
    const int lane  = tid & 31;
    const int w     = tid >> 5;

    const uint32_t base_u  = smem_u32(dynsm);
    const uint32_t actHi_u = base_u + OFF_ACTHI;
    const uint32_t slot_u[2] = { base_u + OFF_SLOT0, base_u + OFF_SLOT1 };

    prefetch_w(slot_u[0], g_Wimg + (size_t)(layer * 4) * (2 * WMAT_ELEMS),
               WSLOT_BYTES / 16, tid);

    if (tid < HDIM) {
        s_w0col[tid] = made_W0[(layer * HDIM + tid) * 2];
        s_b0[tid]    = made_b0[layer * HDIM + tid];
        s_out0[tid]  = TLO + (float)(tile * HDIM + tid) * TDELTA;
    }
    for (int i = tid; i < 4 * HDIM; i += 256)
        s_bias[i >> 7][i & 127] = made_bres[layer * 4 * HDIM + i];
    __syncthreads();

    const int r0 = w * 16 + (lane >> 2);
    const int r1 = r0 + 8;
    const int cB = (lane & 3) * 2;
    const uint32_t o0 = (uint32_t)r0 * ROWB + cB * 2;
    const uint32_t o1 = (uint32_t)r1 * ROWB + cB * 2;

    float H[64];
    {
        float oa = s_out0[r0], ob = s_out0[r1];
        #pragma unroll
        for (int t = 0; t < 16; t++) {
            int c = t * 8 + cB;
            float2 wc = *(const float2*)&s_w0col[c];
            float2 bc = *(const float2*)&s_b0[c];
            float h0 = fmaf(oa, wc.x, bc.x), h1 = fmaf(oa, wc.y, bc.y);
            float h2 = fmaf(ob, wc.x, bc.x), h3 = fmaf(ob, wc.y, bc.y);
            H[t * 4] = h0; H[t * 4 + 1] = h1; H[t * 4 + 2] = h2; H[t * 4 + 3] = h3;
            uint32_t hi0, lo0, hi1, lo1;
            split2(fmaxf(h0, 0.f), fmaxf(h1, 0.f), hi0, lo0);
            split2(fmaxf(h2, 0.f), fmaxf(h3, 0.f), hi1, lo1);
            *(uint32_t*)(dynsm + OFF_ACTHI + o0 + t * 16) = hi0;
            *(uint32_t*)(dynsm + OFF_ACTHI + o1 + t * 16) = hi1;
            *(uint32_t*)(dynsm + OFF_ACTLO + o0 + t * 16) = lo0;
            *(uint32_t*)(dynsm + OFF_ACTLO + o1 + t * 16) = lo1;
        }
    }
    CP_WAIT0();
    __syncthreads();

    const uint32_t aHiBase = actHi_u + (uint32_t)(w * 16 + (lane & 15)) * ROWB
                             + ((lane >> 4) * 16);
    const uint32_t aLoBase = aHiBase + ACT_BYTES;
    const uint32_t bOff    = (uint32_t)(lane & 15) * ROWB + ((lane >> 4) * 16);
    const uint32_t wfOff   = (uint32_t)(lane & 15) * (WF_STRIDE * 2) + ((lane >> 4) * 16);

    #pragma unroll 1
    for (int g = 0; g < 4; g++) {
        if (g < 3)
            prefetch_w(slot_u[(g + 1) & 1],
                       g_Wimg + (size_t)(layer * 4 + g + 1) * (2 * WMAT_ELEMS),
                       WSLOT_BYTES / 16, tid);
        else
            prefetch_w(slot_u[0], g_Wfimg + (size_t)layer * (2 * WF_HALF),
                       WF_BYTES / 16, tid);

        __syncwarp();
        uint32_t Ah[8][4], Al[8][4];
        #pragma unroll
        for (int kc = 0; kc < 8; kc++) {
            ldmA4(Ah[kc], aHiBase + kc * 32);
            ldmA4(Al[kc], aLoBase + kc * 32);
        }
        const uint32_t wbase = slot_u[g & 1] + bOff;

        #pragma unroll
        for (int tp = 0; tp < 8; tp++) {
            float D0[4] = {0.f, 0.f, 0.f, 0.f};
            float D1[4] = {0.f, 0.f, 0.f, 0.f};
            #pragma unroll
            for (int kc = 0; kc < 8; kc++) {
                uint32_t bh[4], bl[4];
                ldmB4t(bh, wbase + kc * (16 * ROWB) + tp * 32);
                ldmB4t(bl, wbase + ACT_BYTES + kc * (16 * ROWB) + tp * 32);
                mmabf(D0, Ah[kc], bh[0], bh[1]);
                mmabf(D0, Al[kc], bh[0], bh[1]);
                mmabf(D0, Ah[kc], bl[0], bl[1]);
                mmabf(D1, Ah[kc], bh[2], bh[3]);
                mmabf(D1, Al[kc], bh[2], bh[3]);
                mmabf(D1, Ah[kc], bl[2], bl[3]);
            }
            #pragma unroll
            for (int q = 0; q < 2; q++) {
                const int t = tp * 2 + q;
                float* D = q ? D1 : D0;
                float2 bb = *(const float2*)&s_bias[g][t * 8 + cB];
                float v0, v1, v2, v3;
                if ((g & 1) == 0) {
                    v0 = fmaxf(D[0] + bb.x, 0.f);
                    v1 = fmaxf(D[1] + bb.y, 0.f);
                    v2 = fmaxf(D[2] + bb.x, 0.f);
                    v3 = fmaxf(D[3] + bb.y, 0.f);
                } else {
                    float n0 = H[t * 4]     + D[0] + bb.x;
                    float n1 = H[t * 4 + 1] + D[1] + bb.y;
                    float n2 = H[t * 4 + 2] + D[2] + bb.x;
                    float n3 = H[t * 4 + 3] + D[3] + bb.y;
                    H[t * 4] = n0; H[t * 4 + 1] = n1;
                    H[t * 4 + 2] = n2; H[t * 4 + 3] = n3;
                    if (g == 3) { v0 = n0; v1 = n1; v2 = n2; v3 = n3; }
                    else { v0 = fmaxf(n0, 0.f); v1 = fmaxf(n1, 0.f);
                           v2 = fmaxf(n2, 0.f); v3 = fmaxf(n3, 0.f); }
                }
                uint32_t hi0, lo0, hi1, lo1;
                split2(v0, v1, hi0, lo0);
                split2(v2, v3, hi1, lo1);
                *(uint32_t*)(dynsm + OFF_ACTHI + o0 + t * 16) = hi0;
                *(uint32_t*)(dynsm + OFF_ACTHI + o1 + t * 16) = hi1;
                *(uint32_t*)(dynsm + OFF_ACTLO + o0 + t * 16) = lo0;
                *(uint32_t*)(dynsm + OFF_ACTLO + o1 + t * 16) = lo1;
            }
        }
        CP_WAIT0();
        __syncthreads();
    }

    // Wf GEMM: p1 = h @ Wf^T
    {
        __syncwarp();
        uint32_t Ah[8][4], Al[8][4];
        #pragma unroll
        for (int kc = 0; kc < 8; kc++) {
            ldmA4(Ah[kc], aHiBase + kc * 32);
            ldmA4(Al[kc], aLoBase + kc * 32);
        }
        const uint32_t wfb = slot_u[0] + wfOff;
        float* p1 = (float*)(dynsm + OFF_P1);
        #pragma unroll
        for (int tp = 0; tp < 2; tp++) {
            float D0[4] = {0.f, 0.f, 0.f, 0.f};
            float D1[4] = {0.f, 0.f, 0.f, 0.f};
            #pragma unroll
            for (int kc = 0; kc < 8; kc++) {
                uint32_t bh[4], bl[4];
                ldmB4t(bh, wfb + kc * (16 * WF_STRIDE * 2) + tp * 32);
                ldmB4t(bl, wfb + 2 * WF_HALF + kc * (16 * WF_STRIDE * 2) + tp * 32);
                mmabf(D0, Ah[kc], bh[0], bh[1]);
                mmabf(D0, Al[kc], bh[0], bh[1]);
                mmabf(D0, Ah[kc], bl[0], bl[1]);
                mmabf(D1, Ah[kc], bh[2], bh[3]);
                mmabf(D1, Al[kc], bh[2], bh[3]);
                mmabf(D1, Ah[kc], bl[2], bl[3]);
            }
            int c0 = tp * 16 + cB;
            p1[r0 * 26 + c0] = D0[0]; p1[r0 * 26 + c0 + 1] = D0[1];
            p1[r1 * 26 + c0] = D0[2]; p1[r1 * 26 + c0 + 1] = D0[3];
            if (tp == 0) {
                p1[r0 * 26 + c0 + 8] = D1[0]; p1[r0 * 26 + c0 + 9] = D1[1];
                p1[r1 * 26 + c0 + 8] = D1[2]; p1[r1 * 26 + c0 + 9] = D1[3];
            }
        }
    }
    __syncthreads();

    if (tid < HDIM) {
        const float* p1r = (const float*)(dynsm + OFF_P1) + tid * 26;
        const float* bf1 = made_bf + layer * (2 * PMVAL) + PMVAL;
        float* trow = g_table + ((size_t)layer * TS + tile * HDIM + tid) * 24;
        #pragma unroll
        for (int m = 0; m < PMVAL; m++) trow[m] = p1r[m] + bf1[m];
        trow[23] = 0.f;
    }
}

// ------------------------- exact MLP fallback (rare) ------------------------
__device__ void made_fallback(unsigned need, float out0_self, int l,
                              const float* __restrict__ W0,
                              const float* __restrict__ b0,
                              const float* __restrict__ Wres,
                              const float* __restrict__ bres,
                              const float* __restrict__ Wf,
                              const float* __restrict__ bf,
                              float* p1out, int lane) {
    while (need) {
        int src = __ffs(need) - 1;
        need &= need - 1;
        float x0 = __shfl_sync(0xffffffffu, out0_self, src);
        float h[4];
        #pragma unroll
        for (int jj = 0; jj < 4; jj++) {
            int j = jj * 32 + lane;
            h[jj] = fmaf(x0, W0[(l * HDIM + j) * 2], b0[l * HDIM + j]);
        }
        #pragma unroll 1
        for (int blk = 0; blk < 2; blk++) {
            float v[4], a1[4], a2[4];
            #pragma unroll
            for (int jj = 0; jj < 4; jj++) v[jj] = fmaxf(h[jj], 0.f);
            const float* Wa = Wres + (size_t)((l * 2 + blk) * 2 + 0) * 16384;
            const float* ba = bres + ((l * 2 + blk) * 2 + 0) * 128;
            #pragma unroll
            for (int jj = 0; jj < 4; jj++) a1[jj] = ba[jj * 32 + lane];
            for (int kk = 0; kk < 4; kk++) {
                float vv = v[kk];
                for (int k2 = 0; k2 < 32; k2++) {
                    float vk = __shfl_sync(0xffffffffu, vv, k2);
                    int k = kk * 32 + k2;
                    #pragma unroll
                    for (int jj = 0; jj < 4; jj++)
                        a1[jj] = fmaf(Wa[(jj * 32 + lane) * 128 + k], vk, a1[jj]);
                }
            }
            #pragma unroll
            for (int jj = 0; jj < 4; jj++) a1[jj] = fmaxf(a1[jj], 0.f);
            const float* Wb = Wres + (size_t)((l * 2 + blk) * 2 + 1) * 16384;
            const float* bb = bres + ((l * 2 + blk) * 2 + 1) * 128;
            #pragma unroll
            for (int jj = 0; jj < 4; jj++) a2[jj] = bb[jj * 32 + lane];
            for (int kk = 0; kk < 4; kk++) {
                float vv = a1[kk];
                for (int k2 = 0; k2 < 32; k2++) {
                    float vk = __shfl_sync(0xffffffffu, vv, k2);
                    int k = kk * 32 + k2;
                    #pragma unroll
                    for (int jj = 0; jj < 4; jj++)
                        a2[jj] = fmaf(Wb[(jj * 32 + lane) * 128 + k], vk, a2[jj]);
                }
            }
            #pragma unroll
            for (int jj = 0; jj < 4; jj++) h[jj] += a2[jj];
        }
        float accp = (lane < PMVAL) ? bf[l * (2 * PMVAL) + PMVAL + lane] : 0.f;
        for (int kk = 0; kk < 4; kk++) {
            float hv = h[kk];
            for (int k2 = 0; k2 < 32; k2++) {
                float vk = __shfl_sync(0xffffffffu, hv, k2);
                int k = kk * 32 + k2;
                if (lane < PMVAL)
                    accp = fmaf(Wf[((size_t)l * (2 * PMVAL) + PMVAL + lane) * 128 + k],
                                vk, accp);
            }
        }
        #pragma unroll
        for (int m = 0; m < PMVAL; m++) {
            float pm = __shfl_sync(0xffffffffu, accp, m);
            if (lane == src) p1out[m] = pm;
        }
    }
}

// ------------------------------ fused flow kernel ---------------------------
__global__ void __launch_bounds__(256)
flow_kernel(const float* __restrict__ z0in, const float* __restrict__ xin,
            const float* __restrict__ sigma,
            const float* __restrict__ n1w1, const float* __restrict__ n1b1,
            const float* __restrict__ n1w2, const float* __restrict__ n1b2,
            const float* __restrict__ n2w1, const float* __restrict__ n2b1,
            const float* __restrict__ n2w2, const float* __restrict__ n2b2,
            const float* __restrict__ made_W0, const float* __restrict__ made_b0,
            const float* __restrict__ made_Wres, const float* __restrict__ made_bres,
            const float* __restrict__ made_Wf, const float* __restrict__ made_bf,
            const float* __restrict__ lu_bias, const int* __restrict__ perms,
            float* __restrict__ out) {
    __shared__ float s1w[32], s1b[32], s1o[64], s1ob[2];
    __shared__ float s2w[128], s2b[32], s2o[64], s2ob[2];
    __shared__ float sld;
    __shared__ float sc_cw[NLAYER][9], sc_w[NLAYER][8], sc_ch[NLAYER][9];
    __shared__ float sc_h[NLAYER][8], sc_d[NLAYER][9];
    __shared__ float sc_invW[NLAYER][4], sc_b2[NLAYER][2];
    __shared__ int   sc_perm[NLAYER][2];

    const int tid  = threadIdx.x;
    const int lane = tid & 31;

    if (tid < 32) { s1w[tid] = n1w1[tid]; s1b[tid] = n1b1[tid]; s2b[tid] = n2b1[tid]; }
    if (tid < 64) { s1o[tid] = n1w2[tid]; s2o[tid] = n2w2[tid]; }
    if (tid < 128) s2w[tid] = n2w1[tid];
    if (tid < 2)  { s1ob[tid] = n1b2[tid]; s2ob[tid] = n2b2[tid]; }
    if (tid == 0) sld = g_ldinit;
    for (int i = tid; i < NLAYER * 9; i += 256) {
        sc_cw[i / 9][i % 9] = g_cw0[i];
        sc_ch[i / 9][i % 9] = g_ch0[i];
        sc_d [i / 9][i % 9] = g_d0[i];
    }
    for (int i = tid; i < NLAYER * 8; i += 256) {
        sc_w[i / 8][i % 8] = g_w0[i];
        sc_h[i / 8][i % 8] = g_h0[i];
    }
    for (int i = tid; i < NLAYER * 4; i += 256) sc_invW[i / 4][i % 4] = g_invW[i];
    for (int i = tid; i < NLAYER * 2; i += 256) {
        sc_b2[i / 2][i % 2]   = lu_bias[i];
        sc_perm[i / 2][i % 2] = perms[i];
    }
    __syncthreads();

    const int row = blockIdx.x * 256 + tid;

    // ---- prelude (fused) ----
    float sg = sigma[row];
    float2 zv = ((const float2*)z0in)[row];
    float2 xv = ((const float2*)xin)[row];
    float t0 = s1ob[0], t1 = s1ob[1];
    #pragma unroll
    for (int j = 0; j < 32; j++) {
        float hv = s1w[j] * sg + s1b[j];
        hv = hv * __frcp_rn(1.f + __expf(-hv));
        t0 += s1o[j] * hv;
        t1 += s1o[32 + j] * hv;
    }
    float zc0 = s2ob[0], zc1 = s2ob[1];
    #pragma unroll
    for (int j = 0; j < 32; j++) {
        float hv = s2w[4 * j] * zv.x + s2w[4 * j + 1] * zv.y
                 + s2w[4 * j + 2] * xv.x + s2w[4 * j + 3] * xv.y + s2b[j];
        hv = hv * __frcp_rn(1.f + __expf(-hv));
        zc0 += s2o[j] * hv;
        zc1 += s2o[32 + j] * hv;
    }
    float z0 = zc0 + t0;
    float z1 = zc1 + t1;
    float ld = sld;

    // ---- 16 layers ----
    #pragma unroll 1
    for (int l = 0; l < NLAYER; l++) {
        float out0, ldp0;
        rqs_reg(z0, sc_cw[l], sc_w[l], sc_ch[l], sc_h[l], sc_d[l], out0, ldp0);

        float p1[24];
        float u = (out0 - TLO) * TINVD;
        bool inr = (u >= 0.f) && (u <= (float)(TS - 2) + 0.999f);
        if (inr) {
            int i = (int)u;
            float f = u - (float)i;
            const float4* ra = (const float4*)(g_table + ((size_t)l * TS + i) * 24);
            const float4* rb = (const float4*)(g_table + ((size_t)l * TS + i + 1) * 24);
            #pragma unroll
            for (int q = 0; q < 6; q++) {
                float4 va = ra[q], vb = rb[q];
                p1[4 * q]     = va.x + f * (vb.x - va.x);
                p1[4 * q + 1] = va.y + f * (vb.y - va.y);
                p1[4 * q + 2] = va.z + f * (vb.z - va.z);
                p1[4 * q + 3] = va.w + f * (vb.w - va.w);
            }
        }
        unsigned need = __ballot_sync(0xffffffffu, !inr);
        if (need)
            made_fallback(need, out0, l, made_W0, made_b0, made_Wres, made_bres,
                          made_Wf, made_bf, p1, lane);

        float out1, ldp1;
        spline1(z1, p1, out1, ldp1);

        ld += ldp0 + ldp1;
        float v0 = out0 - sc_b2[l][0];
        float v1 = out1 - sc_b2[l][1];
        float zz0 = sc_invW[l][0] * v0 + sc_invW[l][1] * v1;
        float zz1 = sc_invW[l][2] * v0 + sc_invW[l][3] * v1;
        z0 = sc_perm[l][0] ? zz1 : zz0;
        z1 = sc_perm[l][1] ? zz1 : zz0;
    }

    ((float2*)out)[row] = make_float2(z0, z1);
    out[2 * BATCH + row] = ld;
}

// ------------------------------ launcher -----------------------------------
extern "C" void kernel_launch(void* const* d_in, const int* in_sizes, int n_in,
                              void* d_out, int out_size) {
    const float* z0      = (const float*)d_in[0];
    const float* x       = (const float*)d_in[1];
    const float* sigma   = (const float*)d_in[2];
    const float* n1_w1   = (const float*)d_in[3];
    const float* n1_b1   = (const float*)d_in[4];
    const float* n1_w2   = (const float*)d_in[5];
    const float* n1_b2   = (const float*)d_in[6];
    const float* n2_w1   = (const float*)d_in[7];
    const float* n2_b1   = (const float*)d_in[8];
    const float* n2_w2   = (const float*)d_in[9];
    const float* n2_b2   = (const float*)d_in[10];
    const float* made_W0 = (const float*)d_in[11];
    const float* made_b0 = (const float*)d_in[12];
    const float* made_Wres = (const float*)d_in[13];
    const float* made_bres = (const float*)d_in[14];
    const float* made_Wf   = (const float*)d_in[15];
    const float* made_bf   = (const float*)d_in[16];
    const float* lu_lower  = (const float*)d_in[17];
    const float* lu_upper  = (const float*)d_in[18];
    const float* lu_diag   = (const float*)d_in[19];
    const float* lu_bias   = (const float*)d_in[20];
    const int*   perms     = (const int*)d_in[21];
    float* out = (float*)d_out;

    cudaFuncSetAttribute(table_build_kernel,
                         cudaFuncAttributeMaxDynamicSharedMemorySize, DYN_SMEM);

    build_wimg_kernel<<<2048, 256>>>(made_Wres, made_Wf);
    setup_kernel<<<1, 32>>>(made_bf, lu_lower, lu_upper, lu_diag);
    table_build_kernel<<<NLAYER * (TS / HDIM), 256, DYN_SMEM>>>(
        made_W0, made_b0, made_bres, made_bf);
    flow_kernel<<<BATCH / 256, 256>>>(
        z0, x, sigma, n1_w1, n1_b1, n1_w2, n1_b2,
        n2_w1, n2_b1, n2_w2, n2_b2,
        made_W0, made_b0, made_Wres, made_bres, made_Wf, made_bf,
        lu_bias, perms, out);
    (void)in_sizes; (void)n_in; (void)out_size;
}